// round 1
// baseline (speedup 1.0000x reference)
#include <cuda_runtime.h>

#define NPTS 100000
#define PCH  96
#define DIMC 192
#define KTAP 27

// ---------------- scratch (static device globals; no allocation) ------------
__device__ float g_v1[NPTS * PCH];       // value branch after conv3+bn+relu
__device__ float g_v2[NPTS * DIMC];      // after 1x1 expand + bn + relu
__device__ float g_choice[NPTS * 24];    // [n][d][m] final attention weights
__device__ float g_agg[NPTS * DIMC];     // aggregated codebook output

// ---------------- sparse-pattern masks --------------------------------------
__constant__ int c_mask_items[3][4][9] = {
  { {0,1,3,6,7,13,-1,-1,-1}, {1,2,9,14,15,17,-1,-1,-1},
    {0,5,6,7,8,10,-1,-1,-1}, {17,19,20,22,23,-1,-1,-1,-1} },
  { {10,11,12,20,21,22,-1,-1,-1}, {1,2,3,4,5,6,10,21,20},
    {3,4,5,6,7,8,9,10,11},        {17,18,19,20,22,23,24,-1,-1} },
  { {0,5,9,13,19,22,-1,-1,-1}, {1,3,7,8,11,16,20,-1,-1},
    {4,6,11,12,18,24,25,-1,-1}, {5,6,10,14,19,23,-1,-1,-1} },
};
__constant__ int c_mask_len[3][4] = {{6,6,6,5},{6,9,9,7},{6,7,7,6}};

// =============================================================================
// K1: v1 = relu( (sum_k gather(x, neis[1][k]) @ w_v1[k]) * bn1_g + bn1_b )
// block: 64 points x 96 cols, 256 threads, thread tile 4x6
// =============================================================================
__global__ __launch_bounds__(256) void k1_conv_v1(
    const float* __restrict__ x, const int* __restrict__ neis,
    const float* __restrict__ w, const float* __restrict__ bng,
    const float* __restrict__ bnb)
{
  extern __shared__ float sm[];
  float* xs = sm;            // [64][100]
  float* ws = sm + 6400;     // [96][96]
  const int tid = threadIdx.x;
  const int n0  = blockIdx.x * 64;
  const int cg  = tid & 15;       // col group: j = cg*6 + jj
  const int pg  = tid >> 4;       // pt group:  p = pg*4 + pp
  const int gp  = tid >> 2, gq = tid & 3;   // gather: row, quarter

  float acc[4][6] = {};

  for (int k = 0; k < KTAP; ++k) {
    // stage W[k] (96x96)
    const float4* wk = (const float4*)(w + k * PCH * PCH);
    #pragma unroll
    for (int i = 0; i < 9; ++i) ((float4*)ws)[tid + i*256] = wk[tid + i*256];
    // gather 64 neighbor rows of x
    {
      int n = n0 + gp;
      int r = NPTS;
      if (n < NPTS) r = neis[(1*KTAP + k) * NPTS + n];
      if (r < NPTS) {
        const float4* src = (const float4*)(x + r * PCH + gq * 24);
        #pragma unroll
        for (int t = 0; t < 6; ++t)
          *(float4*)&xs[gp*100 + gq*24 + t*4] = src[t];
      } else {
        float4 z = make_float4(0.f,0.f,0.f,0.f);
        #pragma unroll
        for (int t = 0; t < 6; ++t)
          *(float4*)&xs[gp*100 + gq*24 + t*4] = z;
      }
    }
    __syncthreads();
    #pragma unroll 2
    for (int c = 0; c < PCH; ++c) {
      float xv[4];
      #pragma unroll
      for (int pp = 0; pp < 4; ++pp) xv[pp] = xs[(pg*4+pp)*100 + c];
      float wv[6];
      #pragma unroll
      for (int q = 0; q < 3; ++q) {
        float2 f = *(const float2*)&ws[c*PCH + cg*6 + q*2];
        wv[q*2] = f.x; wv[q*2+1] = f.y;
      }
      #pragma unroll
      for (int pp = 0; pp < 4; ++pp)
        #pragma unroll
        for (int jj = 0; jj < 6; ++jj)
          acc[pp][jj] = fmaf(xv[pp], wv[jj], acc[pp][jj]);
    }
    __syncthreads();
  }
  #pragma unroll
  for (int pp = 0; pp < 4; ++pp) {
    int n = n0 + pg*4 + pp;
    if (n < NPTS) {
      #pragma unroll
      for (int jj = 0; jj < 6; ++jj) {
        int j = cg*6 + jj;
        g_v1[n*PCH + j] = fmaxf(fmaf(acc[pp][jj], bng[j], bnb[j]), 0.f);
      }
    }
  }
}

// =============================================================================
// K2: v2 = relu( (v1 @ w_v2) * bn2_g + bn2_b )   [100k,96]@[96,192]
// block: 64 points x 192 cols, 256 threads, thread tile 4x12
// =============================================================================
__global__ __launch_bounds__(256) void k2_fc_v2(
    const float* __restrict__ w2, const float* __restrict__ bng,
    const float* __restrict__ bnb)
{
  extern __shared__ float sm[];
  float* vs = sm;           // [64][100]
  float* ws = sm + 6400;    // [96][192]
  const int tid = threadIdx.x;
  const int n0  = blockIdx.x * 64;

  #pragma unroll
  for (int i = 0; i < 18; ++i)
    ((float4*)ws)[tid + i*256] = ((const float4*)w2)[tid + i*256];
  {
    int gp = tid >> 2, gq = tid & 3;
    int n = n0 + gp;
    float4 z = make_float4(0.f,0.f,0.f,0.f);
    #pragma unroll
    for (int t = 0; t < 6; ++t) {
      float4 v = z;
      if (n < NPTS) v = *(const float4*)(g_v1 + n*PCH + gq*24 + t*4);
      *(float4*)&vs[gp*100 + gq*24 + t*4] = v;
    }
  }
  __syncthreads();

  const int cg = tid & 15, pg = tid >> 4;
  float acc[4][12] = {};
  #pragma unroll 2
  for (int c = 0; c < PCH; ++c) {
    float xv[4];
    #pragma unroll
    for (int pp = 0; pp < 4; ++pp) xv[pp] = vs[(pg*4+pp)*100 + c];
    float wv[12];
    #pragma unroll
    for (int q = 0; q < 3; ++q) {
      float4 f = *(const float4*)&ws[c*DIMC + cg*12 + q*4];
      wv[q*4+0]=f.x; wv[q*4+1]=f.y; wv[q*4+2]=f.z; wv[q*4+3]=f.w;
    }
    #pragma unroll
    for (int pp = 0; pp < 4; ++pp)
      #pragma unroll
      for (int jj = 0; jj < 12; ++jj)
        acc[pp][jj] = fmaf(xv[pp], wv[jj], acc[pp][jj]);
  }
  #pragma unroll
  for (int pp = 0; pp < 4; ++pp) {
    int n = n0 + pg*4 + pp;
    if (n < NPTS) {
      #pragma unroll
      for (int jj = 0; jj < 12; ++jj) {
        int j = cg*12 + jj;
        g_v2[n*DIMC + j] = fmaxf(fmaf(acc[pp][jj], bng[j], bnb[j]), 0.f);
      }
    }
  }
}

// =============================================================================
// K3: query convs (Cout=8, all 3 dilations) + softmax over M + sparse-pattern
// double softmax -> g_choice[n][d][m]
// block: 128 points, 256 threads = (point, m-half); thread holds acc[3][4]
// =============================================================================
__global__ __launch_bounds__(256) void k3_choice(
    const float* __restrict__ x, const int* __restrict__ neis,
    const float* __restrict__ qw)
{
  extern __shared__ float sm[];
  float* xst = sm;            // [96][129] transposed gather tile
  float* qws = sm + 12384;    // [96][8]
  const int tid = threadIdx.x;
  const int n0  = blockIdx.x * 128;
  const int p   = tid & 127;
  const int mh  = tid >> 7;            // m half: m = mh*4 + j
  const int gp  = tid >> 1, gh = tid & 1;

  float acc[3][4] = {};

  #pragma unroll
  for (int d = 0; d < 3; ++d) {
    #pragma unroll 1
    for (int k = 0; k < KTAP; ++k) {
      __syncthreads();
      if (tid < 192)
        ((float4*)qws)[tid] = ((const float4*)(qw + (d*KTAP + k) * (PCH*8)))[tid];
      {
        int n = n0 + gp;
        int r = NPTS;
        if (n < NPTS) r = neis[(d*KTAP + k)*NPTS + n];
        if (r < NPTS) {
          const float4* src = (const float4*)(x + r*PCH + gh*48);
          #pragma unroll
          for (int q = 0; q < 12; ++q) {
            float4 v = src[q];
            int c = gh*48 + q*4;
            xst[(c+0)*129 + gp] = v.x;
            xst[(c+1)*129 + gp] = v.y;
            xst[(c+2)*129 + gp] = v.z;
            xst[(c+3)*129 + gp] = v.w;
          }
        } else {
          #pragma unroll
          for (int q = 0; q < 48; ++q) xst[(gh*48 + q)*129 + gp] = 0.f;
        }
      }
      __syncthreads();
      #pragma unroll 4
      for (int c = 0; c < PCH; ++c) {
        float xv = xst[c*129 + p];
        float4 wv = *(const float4*)&qws[c*8 + mh*4];
        acc[d][0] = fmaf(xv, wv.x, acc[d][0]);
        acc[d][1] = fmaf(xv, wv.y, acc[d][1]);
        acc[d][2] = fmaf(xv, wv.z, acc[d][2]);
        acc[d][3] = fmaf(xv, wv.w, acc[d][3]);
      }
    }
  }
  __syncthreads();
  float* qsm = sm;   // reuse tile region for qs exchange: [128][25]
  #pragma unroll
  for (int d = 0; d < 3; ++d)
    #pragma unroll
    for (int j = 0; j < 4; ++j)
      qsm[p*25 + d*8 + mh*4 + j] = acc[d][j];
  __syncthreads();

  if (tid < 128) {
    int n = n0 + tid;
    if (n < NPTS) {
      float t1[3][8];
      #pragma unroll
      for (int d = 0; d < 3; ++d) {
        unsigned pb = 0;
        #pragma unroll 1
        for (int k = 0; k < KTAP; ++k)
          pb |= (unsigned)(neis[(d*KTAP + k)*NPTS + n] < NPTS) << k;
        float v[8];
        #pragma unroll
        for (int mi = 0; mi < 4; ++mi) {
          unsigned ex = 0;
          #pragma unroll
          for (int t = 0; t < 9; ++t) {
            int it = c_mask_items[d][mi][t];
            if (it >= 0) ex |= (1u << it);
          }
          float keepinv = 1.f / (float)(27 - c_mask_len[d][mi]);
          float spv = (float)__popc(pb & ~ex & 0x7FFFFFFu) * keepinv;
          v[mi] = (spv + 1e-3f) * 5.f;
        }
        #pragma unroll
        for (int mi = 4; mi < 8; ++mi) v[mi] = 5e-3f;
        float mx = v[0];
        #pragma unroll
        for (int m = 1; m < 8; ++m) mx = fmaxf(mx, v[m]);
        float s = 0.f;
        #pragma unroll
        for (int m = 0; m < 8; ++m) { v[m] = __expf(v[m] - mx); s += v[m]; }
        float inv = 1.f / s;
        #pragma unroll
        for (int m = 0; m < 8; ++m) t1[d][m] = v[m] * inv;
      }
      // second softmax over D (in place)
      #pragma unroll
      for (int m = 0; m < 8; ++m) {
        float a0 = (t1[0][m] + 1e-3f) * 5.f;
        float a1 = (t1[1][m] + 1e-3f) * 5.f;
        float a2 = (t1[2][m] + 1e-3f) * 5.f;
        float mx = fmaxf(a0, fmaxf(a1, a2));
        float e0 = __expf(a0 - mx), e1 = __expf(a1 - mx), e2 = __expf(a2 - mx);
        float inv = 1.f / (e0 + e1 + e2);
        t1[0][m] = e0 * inv; t1[1][m] = e1 * inv; t1[2][m] = e2 * inv;
      }
      // softmax(qs / sqrt(2)) over M, times pattern
      #pragma unroll
      for (int d = 0; d < 3; ++d) {
        float sv[8];
        float mx = -1e30f;
        #pragma unroll
        for (int m = 0; m < 8; ++m) {
          sv[m] = qsm[tid*25 + d*8 + m] * 0.70710678118654752f;
          mx = fmaxf(mx, sv[m]);
        }
        float s = 0.f;
        #pragma unroll
        for (int m = 0; m < 8; ++m) { sv[m] = __expf(sv[m] - mx); s += sv[m]; }
        float inv = 1.f / s;
        #pragma unroll
        for (int m = 0; m < 8; ++m)
          g_choice[n*24 + d*8 + m] = sv[m] * inv * t1[d][m];
      }
    }
  }
}

// =============================================================================
// K4: agg[n,c] = sum_d choice[n,d,c/24] * sum_k cb_kern[d,k,c] * v2[neis[d,k,n],c]
// warp-per-point, lane-strided channels (6 per lane) -> coalesced 128B gathers
// =============================================================================
__global__ __launch_bounds__(256) void k4_agg(
    const int* __restrict__ neis, const float* __restrict__ cb)
{
  extern __shared__ float ks[];   // 3*27*192 = 15552 floats
  for (int i = threadIdx.x; i < 3888; i += 256)
    ((float4*)ks)[i] = ((const float4*)cb)[i];
  __syncthreads();

  const int lane = threadIdx.x & 31;
  const int w    = threadIdx.x >> 5;
  const int n0   = blockIdx.x * 128 + w * 16;

  for (int pi = 0; pi < 16; ++pi) {
    int n = n0 + pi;
    if (n >= NPTS) break;
    float agg[6] = {0.f,0.f,0.f,0.f,0.f,0.f};
    #pragma unroll
    for (int d = 0; d < 3; ++d) {
      float pd[6] = {0.f,0.f,0.f,0.f,0.f,0.f};
      const int* nd = neis + d*KTAP*NPTS + n;
      #pragma unroll 1
      for (int k = 0; k < KTAP; ++k) {
        int r = nd[k*NPTS];
        if (r < NPTS) {
          const float* vr = g_v2 + r*DIMC + lane;
          const float* kk = ks + (d*KTAP + k)*DIMC + lane;
          #pragma unroll
          for (int i = 0; i < 6; ++i)
            pd[i] = fmaf(kk[32*i], vr[32*i], pd[i]);
        }
      }
      #pragma unroll
      for (int i = 0; i < 6; ++i) {
        int c = lane + 32*i;
        agg[i] += pd[i] * g_choice[n*24 + d*8 + (c/24)];
      }
    }
    #pragma unroll
    for (int i = 0; i < 6; ++i)
      g_agg[n*DIMC + lane + 32*i] = agg[i];
  }
}

// =============================================================================
// K5: out = relu( (agg @ out_w) * out_bn_g + out_bn_b ) + x
// [100k,192]@[192,96]; two 96-wide inner chunks, thread tile 4x6
// =============================================================================
__global__ __launch_bounds__(256) void k5_out(
    const float* __restrict__ x, const float* __restrict__ ow,
    const float* __restrict__ bng, const float* __restrict__ bnb,
    float* __restrict__ out)
{
  extern __shared__ float sm[];
  float* vs = sm;          // [64][100]
  float* ws = sm + 6400;   // [96][96]
  const int tid = threadIdx.x;
  const int n0  = blockIdx.x * 64;
  const int cg  = tid & 15, pg = tid >> 4;
  const int gp  = tid >> 2, gq = tid & 3;

  float acc[4][6] = {};
  for (int h = 0; h < 2; ++h) {
    #pragma unroll
    for (int i = 0; i < 9; ++i)
      ((float4*)ws)[tid + i*256] = ((const float4*)(ow + h*9216))[tid + i*256];
    {
      int n = n0 + gp;
      float4 z = make_float4(0.f,0.f,0.f,0.f);
      #pragma unroll
      for (int t = 0; t < 6; ++t) {
        float4 v = z;
        if (n < NPTS) v = *(const float4*)(g_agg + n*DIMC + h*96 + gq*24 + t*4);
        *(float4*)&vs[gp*100 + gq*24 + t*4] = v;
      }
    }
    __syncthreads();
    #pragma unroll 2
    for (int c = 0; c < PCH; ++c) {
      float xv[4];
      #pragma unroll
      for (int pp = 0; pp < 4; ++pp) xv[pp] = vs[(pg*4+pp)*100 + c];
      float wv[6];
      #pragma unroll
      for (int q = 0; q < 3; ++q) {
        float2 f = *(const float2*)&ws[c*PCH + cg*6 + q*2];
        wv[q*2] = f.x; wv[q*2+1] = f.y;
      }
      #pragma unroll
      for (int pp = 0; pp < 4; ++pp)
        #pragma unroll
        for (int jj = 0; jj < 6; ++jj)
          acc[pp][jj] = fmaf(xv[pp], wv[jj], acc[pp][jj]);
    }
    __syncthreads();
  }
  #pragma unroll
  for (int pp = 0; pp < 4; ++pp) {
    int n = n0 + pg*4 + pp;
    if (n < NPTS) {
      #pragma unroll
      for (int jj = 0; jj < 6; ++jj) {
        int j = cg*6 + jj;
        float v = fmaxf(fmaf(acc[pp][jj], bng[j], bnb[j]), 0.f);
        out[n*PCH + j] = v + x[n*PCH + j];
      }
    }
  }
}

// =============================================================================
extern "C" void kernel_launch(void* const* d_in, const int* in_sizes, int n_in,
                              void* d_out, int out_size)
{
  const float* x    = (const float*)d_in[0];
  const int*   neis = (const int*)  d_in[1];
  const float* w_v1 = (const float*)d_in[2];
  const float* bn1g = (const float*)d_in[3];
  const float* bn1b = (const float*)d_in[4];
  const float* w_v2 = (const float*)d_in[5];
  const float* bn2g = (const float*)d_in[6];
  const float* bn2b = (const float*)d_in[7];
  const float* q_w  = (const float*)d_in[8];
  const float* cbk  = (const float*)d_in[9];
  const float* outw = (const float*)d_in[10];
  const float* obng = (const float*)d_in[11];
  const float* obnb = (const float*)d_in[12];
  float* out = (float*)d_out;

  const int SM1 = (6400 + 9216)  * 4;   // 62464
  const int SM2 = (6400 + 18432) * 4;   // 99328
  const int SM3 = (12384 + 768)  * 4;   // 52608
  const int SM4 = 15552 * 4;            // 62208
  const int SM5 = (6400 + 9216)  * 4;   // 62464

  cudaFuncSetAttribute(k1_conv_v1, cudaFuncAttributeMaxDynamicSharedMemorySize, SM1);
  cudaFuncSetAttribute(k2_fc_v2,   cudaFuncAttributeMaxDynamicSharedMemorySize, SM2);
  cudaFuncSetAttribute(k3_choice,  cudaFuncAttributeMaxDynamicSharedMemorySize, SM3);
  cudaFuncSetAttribute(k4_agg,     cudaFuncAttributeMaxDynamicSharedMemorySize, SM4);
  cudaFuncSetAttribute(k5_out,     cudaFuncAttributeMaxDynamicSharedMemorySize, SM5);

  k1_conv_v1<<<(NPTS + 63) / 64,   256, SM1>>>(x, neis, w_v1, bn1g, bn1b);
  k2_fc_v2  <<<(NPTS + 63) / 64,   256, SM2>>>(w_v2, bn2g, bn2b);
  k3_choice <<<(NPTS + 127) / 128, 256, SM3>>>(x, neis, q_w);
  k4_agg    <<<(NPTS + 127) / 128, 256, SM4>>>(neis, cbk);
  k5_out    <<<(NPTS + 63) / 64,   256, SM5>>>(x, outw, obng, obnb, out);
}

// round 3
// speedup vs baseline: 1.2436x; 1.2436x over previous
#include <cuda_runtime.h>

#define NPTS 100000
#define PCH  96
#define DIMC 192
#define KTAP 27

// ---------------- scratch (static device globals; no allocation) ------------
__device__ float g_v1[NPTS * PCH];       // value branch after conv3+bn+relu
__device__ float g_v2[NPTS * DIMC];      // after 1x1 expand + bn + relu
__device__ float g_choice[NPTS * 24];    // [n][d][m] final attention weights
__device__ float g_agg[NPTS * DIMC];     // aggregated codebook output

// ---------------- sparse-pattern masks --------------------------------------
__constant__ int c_mask_items[3][4][9] = {
  { {0,1,3,6,7,13,-1,-1,-1}, {1,2,9,14,15,17,-1,-1,-1},
    {0,5,6,7,8,10,-1,-1,-1}, {17,19,20,22,23,-1,-1,-1,-1} },
  { {10,11,12,20,21,22,-1,-1,-1}, {1,2,3,4,5,6,10,21,20},
    {3,4,5,6,7,8,9,10,11},        {17,18,19,20,22,23,24,-1,-1} },
  { {0,5,9,13,19,22,-1,-1,-1}, {1,3,7,8,11,16,20,-1,-1},
    {4,6,11,12,18,24,25,-1,-1}, {5,6,10,14,19,23,-1,-1,-1} },
};
__constant__ int c_mask_len[3][4] = {{6,6,6,5},{6,9,9,7},{6,7,7,6}};

// ---------------- tf32 mma.sync helper (sm_80+ baseline feature) -------------
__device__ __forceinline__ void mma16818(float* d, const unsigned* a,
                                         const unsigned* b) {
  asm volatile(
    "mma.sync.aligned.m16n8k8.row.col.f32.tf32.tf32.f32 "
    "{%0,%1,%2,%3}, {%4,%5,%6,%7}, {%8,%9}, {%0,%1,%2,%3};"
    : "+f"(d[0]), "+f"(d[1]), "+f"(d[2]), "+f"(d[3])
    : "r"(a[0]), "r"(a[1]), "r"(a[2]), "r"(a[3]), "r"(b[0]), "r"(b[1]));
}

// =============================================================================
// K1 (tf32 tensor): v1 = relu(BN( sum_k gather(x,neis[1][k]) @ W[k] ))
// Block tile 128x96; 8 warps = 4(M) x 2(N); warp tile 32x48 (2x6 mma frags).
// A smem [128][100] f32 (pad 100: conflict-free A-frag LDS);
// B smem [96][104]  f32 (pad 104: conflict-free B-frag LDS).
// K loop: 27 taps x 12 k8-steps; B = w_v1[k] used directly ([Cin][Cout]=KxN).
// =============================================================================
#define K1_APAD 100
#define K1_BPAD 104
#define K1_SMEM ((128*K1_APAD + 96*K1_BPAD) * 4)   // 91136 bytes

__global__ __launch_bounds__(256) void k1_mma(
    const float* __restrict__ x, const int* __restrict__ neis,
    const float* __restrict__ w, const float* __restrict__ bng,
    const float* __restrict__ bnb)
{
  extern __shared__ float sm[];
  float* As = sm;                       // [128][100]
  float* Bs = sm + 128 * K1_APAD;       // [96][104]

  const int tid  = threadIdx.x;
  const int lane = tid & 31;
  const int wid  = tid >> 5;
  const int wm   = wid & 3;             // M warp: rows wm*32..+32
  const int wn   = wid >> 2;            // N warp: cols wn*48..+48
  const int n0   = blockIdx.x * 128;

  const int arow  = tid >> 1;           // gather: 2 threads per A row
  const int ahalf = tid & 1;
  const float4 z4 = make_float4(0.f, 0.f, 0.f, 0.f);

  float d[2][6][4] = {};

  for (int k = 0; k < KTAP; ++k) {
    int nr;
    {
      int n = n0 + arow;
      nr = (n < NPTS) ? neis[(KTAP + k) * NPTS + n] : NPTS;  // dilation idx 1
    }
    __syncthreads();   // previous tap's compute done before restaging
    // ---- stage A: 128 gathered rows x 96 ch
    {
      const float4* srcA = (const float4*)(x + (size_t)nr * PCH + ahalf * 48);
      float* dstA = As + arow * K1_APAD + ahalf * 48;
      if (nr < NPTS) {
        #pragma unroll
        for (int i = 0; i < 12; ++i) *(float4*)(dstA + i * 4) = srcA[i];
      } else {
        #pragma unroll
        for (int i = 0; i < 12; ++i) *(float4*)(dstA + i * 4) = z4;
      }
    }
    // ---- stage B: w_v1[k] 96x96 (K x N)
    {
      const float4* srcB = (const float4*)(w + k * PCH * PCH);
      #pragma unroll
      for (int j = 0; j < 9; ++j) {
        int idx = tid + j * 256;          // 2304 float4
        int row = idx / 24, q = idx % 24;
        *(float4*)(Bs + row * K1_BPAD + q * 4) = srcB[idx];
      }
    }
    __syncthreads();
    // ---- compute: 12 k8-steps
    #pragma unroll 2
    for (int ks = 0; ks < 12; ++ks) {
      unsigned a[2][4];
      {
        int c = ks * 8 + (lane & 3);
        #pragma unroll
        for (int mi = 0; mi < 2; ++mi) {
          int r = wm * 32 + mi * 16 + (lane >> 2);
          a[mi][0] = __float_as_uint(As[r * K1_APAD + c]);
          a[mi][1] = __float_as_uint(As[(r + 8) * K1_APAD + c]);
          a[mi][2] = __float_as_uint(As[r * K1_APAD + c + 4]);
          a[mi][3] = __float_as_uint(As[(r + 8) * K1_APAD + c + 4]);
        }
      }
      unsigned bf[6][2];
      {
        int br = ks * 8 + (lane & 3);
        int bc = wn * 48 + (lane >> 2);
        #pragma unroll
        for (int ni = 0; ni < 6; ++ni) {
          bf[ni][0] = __float_as_uint(Bs[br * K1_BPAD + bc + ni * 8]);
          bf[ni][1] = __float_as_uint(Bs[(br + 4) * K1_BPAD + bc + ni * 8]);
        }
      }
      #pragma unroll
      for (int mi = 0; mi < 2; ++mi)
        #pragma unroll
        for (int ni = 0; ni < 6; ++ni)
          mma16818(d[mi][ni], a[mi], bf[ni]);
    }
  }

  // ---- epilogue: BN + ReLU, direct store (float2 per row-half)
  #pragma unroll
  for (int mi = 0; mi < 2; ++mi) {
    int r0 = n0 + wm * 32 + mi * 16 + (lane >> 2);
    #pragma unroll
    for (int ni = 0; ni < 6; ++ni) {
      int c = wn * 48 + ni * 8 + (lane & 3) * 2;
      float g0 = __ldg(&bng[c]),     b0 = __ldg(&bnb[c]);
      float g1 = __ldg(&bng[c + 1]), b1 = __ldg(&bnb[c + 1]);
      if (r0 < NPTS) {
        float2 v;
        v.x = fmaxf(fmaf(d[mi][ni][0], g0, b0), 0.f);
        v.y = fmaxf(fmaf(d[mi][ni][1], g1, b1), 0.f);
        *(float2*)&g_v1[(size_t)r0 * PCH + c] = v;
      }
      if (r0 + 8 < NPTS) {
        float2 v;
        v.x = fmaxf(fmaf(d[mi][ni][2], g0, b0), 0.f);
        v.y = fmaxf(fmaf(d[mi][ni][3], g1, b1), 0.f);
        *(float2*)&g_v1[(size_t)(r0 + 8) * PCH + c] = v;
      }
    }
  }
}

// =============================================================================
// K2: v2 = relu( (v1 @ w_v2) * bn2_g + bn2_b )   [100k,96]@[96,192]
// =============================================================================
__global__ __launch_bounds__(256) void k2_fc_v2(
    const float* __restrict__ w2, const float* __restrict__ bng,
    const float* __restrict__ bnb)
{
  extern __shared__ float sm[];
  float* vs = sm;           // [64][100]
  float* ws = sm + 6400;    // [96][192]
  const int tid = threadIdx.x;
  const int n0  = blockIdx.x * 64;

  #pragma unroll
  for (int i = 0; i < 18; ++i)
    ((float4*)ws)[tid + i*256] = ((const float4*)w2)[tid + i*256];
  {
    int gp = tid >> 2, gq = tid & 3;
    int n = n0 + gp;
    float4 z = make_float4(0.f,0.f,0.f,0.f);
    #pragma unroll
    for (int t = 0; t < 6; ++t) {
      float4 v = z;
      if (n < NPTS) v = *(const float4*)(g_v1 + n*PCH + gq*24 + t*4);
      *(float4*)&vs[gp*100 + gq*24 + t*4] = v;
    }
  }
  __syncthreads();

  const int cg = tid & 15, pg = tid >> 4;
  float acc[4][12] = {};
  #pragma unroll 2
  for (int c = 0; c < PCH; ++c) {
    float xv[4];
    #pragma unroll
    for (int pp = 0; pp < 4; ++pp) xv[pp] = vs[(pg*4+pp)*100 + c];
    float wv[12];
    #pragma unroll
    for (int q = 0; q < 3; ++q) {
      float4 f = *(const float4*)&ws[c*DIMC + cg*12 + q*4];
      wv[q*4+0]=f.x; wv[q*4+1]=f.y; wv[q*4+2]=f.z; wv[q*4+3]=f.w;
    }
    #pragma unroll
    for (int pp = 0; pp < 4; ++pp)
      #pragma unroll
      for (int jj = 0; jj < 12; ++jj)
        acc[pp][jj] = fmaf(xv[pp], wv[jj], acc[pp][jj]);
  }
  #pragma unroll
  for (int pp = 0; pp < 4; ++pp) {
    int n = n0 + pg*4 + pp;
    if (n < NPTS) {
      #pragma unroll
      for (int jj = 0; jj < 12; ++jj) {
        int j = cg*12 + jj;
        g_v2[n*DIMC + j] = fmaxf(fmaf(acc[pp][jj], bng[j], bnb[j]), 0.f);
      }
    }
  }
}

// =============================================================================
// K3: query convs (Cout=8, all 3 dilations) + softmax over M + sparse-pattern
// double softmax -> g_choice[n][d][m]
// =============================================================================
__global__ __launch_bounds__(256) void k3_choice(
    const float* __restrict__ x, const int* __restrict__ neis,
    const float* __restrict__ qw)
{
  extern __shared__ float sm[];
  float* xst = sm;            // [96][129] transposed gather tile
  float* qws = sm + 12384;    // [96][8]
  const int tid = threadIdx.x;
  const int n0  = blockIdx.x * 128;
  const int p   = tid & 127;
  const int mh  = tid >> 7;            // m half: m = mh*4 + j
  const int gp  = tid >> 1, gh = tid & 1;

  float acc[3][4] = {};

  #pragma unroll
  for (int d = 0; d < 3; ++d) {
    #pragma unroll 1
    for (int k = 0; k < KTAP; ++k) {
      __syncthreads();
      if (tid < 192)
        ((float4*)qws)[tid] = ((const float4*)(qw + (d*KTAP + k) * (PCH*8)))[tid];
      {
        int n = n0 + gp;
        int r = NPTS;
        if (n < NPTS) r = neis[(d*KTAP + k)*NPTS + n];
        if (r < NPTS) {
          const float4* src = (const float4*)(x + r*PCH + gh*48);
          #pragma unroll
          for (int q = 0; q < 12; ++q) {
            float4 v = src[q];
            int c = gh*48 + q*4;
            xst[(c+0)*129 + gp] = v.x;
            xst[(c+1)*129 + gp] = v.y;
            xst[(c+2)*129 + gp] = v.z;
            xst[(c+3)*129 + gp] = v.w;
          }
        } else {
          #pragma unroll
          for (int q = 0; q < 48; ++q) xst[(gh*48 + q)*129 + gp] = 0.f;
        }
      }
      __syncthreads();
      #pragma unroll 4
      for (int c = 0; c < PCH; ++c) {
        float xv = xst[c*129 + p];
        float4 wv = *(const float4*)&qws[c*8 + mh*4];
        acc[d][0] = fmaf(xv, wv.x, acc[d][0]);
        acc[d][1] = fmaf(xv, wv.y, acc[d][1]);
        acc[d][2] = fmaf(xv, wv.z, acc[d][2]);
        acc[d][3] = fmaf(xv, wv.w, acc[d][3]);
      }
    }
  }
  __syncthreads();
  float* qsm = sm;   // reuse tile region for qs exchange: [128][25]
  #pragma unroll
  for (int d = 0; d < 3; ++d)
    #pragma unroll
    for (int j = 0; j < 4; ++j)
      qsm[p*25 + d*8 + mh*4 + j] = acc[d][j];
  __syncthreads();

  if (tid < 128) {
    int n = n0 + tid;
    if (n < NPTS) {
      float t1[3][8];
      #pragma unroll
      for (int d = 0; d < 3; ++d) {
        unsigned pb = 0;
        #pragma unroll 1
        for (int k = 0; k < KTAP; ++k)
          pb |= (unsigned)(neis[(d*KTAP + k)*NPTS + n] < NPTS) << k;
        float v[8];
        #pragma unroll
        for (int mi = 0; mi < 4; ++mi) {
          unsigned ex = 0;
          #pragma unroll
          for (int t = 0; t < 9; ++t) {
            int it = c_mask_items[d][mi][t];
            if (it >= 0) ex |= (1u << it);
          }
          float keepinv = 1.f / (float)(27 - c_mask_len[d][mi]);
          float spv = (float)__popc(pb & ~ex & 0x7FFFFFFu) * keepinv;
          v[mi] = (spv + 1e-3f) * 5.f;
        }
        #pragma unroll
        for (int mi = 4; mi < 8; ++mi) v[mi] = 5e-3f;
        float mx = v[0];
        #pragma unroll
        for (int m = 1; m < 8; ++m) mx = fmaxf(mx, v[m]);
        float s = 0.f;
        #pragma unroll
        for (int m = 0; m < 8; ++m) { v[m] = __expf(v[m] - mx); s += v[m]; }
        float inv = 1.f / s;
        #pragma unroll
        for (int m = 0; m < 8; ++m) t1[d][m] = v[m] * inv;
      }
      #pragma unroll
      for (int m = 0; m < 8; ++m) {
        float a0 = (t1[0][m] + 1e-3f) * 5.f;
        float a1 = (t1[1][m] + 1e-3f) * 5.f;
        float a2 = (t1[2][m] + 1e-3f) * 5.f;
        float mx = fmaxf(a0, fmaxf(a1, a2));
        float e0 = __expf(a0 - mx), e1 = __expf(a1 - mx), e2 = __expf(a2 - mx);
        float inv = 1.f / (e0 + e1 + e2);
        t1[0][m] = e0 * inv; t1[1][m] = e1 * inv; t1[2][m] = e2 * inv;
      }
      #pragma unroll
      for (int d = 0; d < 3; ++d) {
        float sv[8];
        float mx = -1e30f;
        #pragma unroll
        for (int m = 0; m < 8; ++m) {
          sv[m] = qsm[tid*25 + d*8 + m] * 0.70710678118654752f;
          mx = fmaxf(mx, sv[m]);
        }
        float s = 0.f;
        #pragma unroll
        for (int m = 0; m < 8; ++m) { sv[m] = __expf(sv[m] - mx); s += sv[m]; }
        float inv = 1.f / s;
        #pragma unroll
        for (int m = 0; m < 8; ++m)
          g_choice[n*24 + d*8 + m] = sv[m] * inv * t1[d][m];
      }
    }
  }
}

// =============================================================================
// K4: agg[n,c] = sum_d choice[n,d,c/24] * sum_k cb_kern[d,k,c] * v2[neis[d,k,n],c]
// =============================================================================
__global__ __launch_bounds__(256) void k4_agg(
    const int* __restrict__ neis, const float* __restrict__ cb)
{
  extern __shared__ float ks[];   // 3*27*192 = 15552 floats
  for (int i = threadIdx.x; i < 3888; i += 256)
    ((float4*)ks)[i] = ((const float4*)cb)[i];
  __syncthreads();

  const int lane = threadIdx.x & 31;
  const int w    = threadIdx.x >> 5;
  const int n0   = blockIdx.x * 128 + w * 16;

  for (int pi = 0; pi < 16; ++pi) {
    int n = n0 + pi;
    if (n >= NPTS) break;
    float agg[6] = {0.f,0.f,0.f,0.f,0.f,0.f};
    #pragma unroll
    for (int d = 0; d < 3; ++d) {
      float pd[6] = {0.f,0.f,0.f,0.f,0.f,0.f};
      const int* nd = neis + d*KTAP*NPTS + n;
      #pragma unroll 1
      for (int k = 0; k < KTAP; ++k) {
        int r = nd[k*NPTS];
        if (r < NPTS) {
          const float* vr = g_v2 + r*DIMC + lane;
          const float* kk = ks + (d*KTAP + k)*DIMC + lane;
          #pragma unroll
          for (int i = 0; i < 6; ++i)
            pd[i] = fmaf(kk[32*i], vr[32*i], pd[i]);
        }
      }
      #pragma unroll
      for (int i = 0; i < 6; ++i) {
        int c = lane + 32*i;
        agg[i] += pd[i] * g_choice[n*24 + d*8 + (c/24)];
      }
    }
    #pragma unroll
    for (int i = 0; i < 6; ++i)
      g_agg[n*DIMC + lane + 32*i] = agg[i];
  }
}

// =============================================================================
// K5: out = relu( (agg @ out_w) * out_bn_g + out_bn_b ) + x
// =============================================================================
__global__ __launch_bounds__(256) void k5_out(
    const float* __restrict__ x, const float* __restrict__ ow,
    const float* __restrict__ bng, const float* __restrict__ bnb,
    float* __restrict__ out)
{
  extern __shared__ float sm[];
  float* vs = sm;          // [64][100]
  float* ws = sm + 6400;   // [96][96]
  const int tid = threadIdx.x;
  const int n0  = blockIdx.x * 64;
  const int cg  = tid & 15, pg = tid >> 4;
  const int gp  = tid >> 2, gq = tid & 3;

  float acc[4][6] = {};
  for (int h = 0; h < 2; ++h) {
    #pragma unroll
    for (int i = 0; i < 9; ++i)
      ((float4*)ws)[tid + i*256] = ((const float4*)(ow + h*9216))[tid + i*256];
    {
      int n = n0 + gp;
      float4 z = make_float4(0.f,0.f,0.f,0.f);
      #pragma unroll
      for (int t = 0; t < 6; ++t) {
        float4 v = z;
        if (n < NPTS) v = *(const float4*)(g_agg + n*DIMC + h*96 + gq*24 + t*4);
        *(float4*)&vs[gp*100 + gq*24 + t*4] = v;
      }
    }
    __syncthreads();
    #pragma unroll 2
    for (int c = 0; c < PCH; ++c) {
      float xv[4];
      #pragma unroll
      for (int pp = 0; pp < 4; ++pp) xv[pp] = vs[(pg*4+pp)*100 + c];
      float wv[6];
      #pragma unroll
      for (int q = 0; q < 3; ++q) {
        float2 f = *(const float2*)&ws[c*PCH + cg*6 + q*2];
        wv[q*2] = f.x; wv[q*2+1] = f.y;
      }
      #pragma unroll
      for (int pp = 0; pp < 4; ++pp)
        #pragma unroll
        for (int jj = 0; jj < 6; ++jj)
          acc[pp][jj] = fmaf(xv[pp], wv[jj], acc[pp][jj]);
    }
    __syncthreads();
  }
  #pragma unroll
  for (int pp = 0; pp < 4; ++pp) {
    int n = n0 + pg*4 + pp;
    if (n < NPTS) {
      #pragma unroll
      for (int jj = 0; jj < 6; ++jj) {
        int j = cg*6 + jj;
        float v = fmaxf(fmaf(acc[pp][jj], bng[j], bnb[j]), 0.f);
        out[n*PCH + j] = v + x[n*PCH + j];
      }
    }
  }
}

// =============================================================================
extern "C" void kernel_launch(void* const* d_in, const int* in_sizes, int n_in,
                              void* d_out, int out_size)
{
  const float* x    = (const float*)d_in[0];
  const int*   neis = (const int*)  d_in[1];
  const float* w_v1 = (const float*)d_in[2];
  const float* bn1g = (const float*)d_in[3];
  const float* bn1b = (const float*)d_in[4];
  const float* w_v2 = (const float*)d_in[5];
  const float* bn2g = (const float*)d_in[6];
  const float* bn2b = (const float*)d_in[7];
  const float* q_w  = (const float*)d_in[8];
  const float* cbk  = (const float*)d_in[9];
  const float* outw = (const float*)d_in[10];
  const float* obng = (const float*)d_in[11];
  const float* obnb = (const float*)d_in[12];
  float* out = (float*)d_out;

  const int SM2 = (6400 + 18432) * 4;   // 99328
  const int SM3 = (12384 + 768)  * 4;   // 52608
  const int SM4 = 15552 * 4;            // 62208
  const int SM5 = (6400 + 9216)  * 4;   // 62464

  cudaFuncSetAttribute(k1_mma,   cudaFuncAttributeMaxDynamicSharedMemorySize, K1_SMEM);
  cudaFuncSetAttribute(k2_fc_v2, cudaFuncAttributeMaxDynamicSharedMemorySize, SM2);
  cudaFuncSetAttribute(k3_choice,cudaFuncAttributeMaxDynamicSharedMemorySize, SM3);
  cudaFuncSetAttribute(k4_agg,   cudaFuncAttributeMaxDynamicSharedMemorySize, SM4);
  cudaFuncSetAttribute(k5_out,   cudaFuncAttributeMaxDynamicSharedMemorySize, SM5);

  k1_mma    <<<(NPTS + 127) / 128, 256, K1_SMEM>>>(x, neis, w_v1, bn1g, bn1b);
  k2_fc_v2  <<<(NPTS + 63) / 64,   256, SM2>>>(w_v2, bn2g, bn2b);
  k3_choice <<<(NPTS + 127) / 128, 256, SM3>>>(x, neis, q_w);
  k4_agg    <<<(NPTS + 127) / 128, 256, SM4>>>(neis, cbk);
  k5_out    <<<(NPTS + 63) / 64,   256, SM5>>>(x, outw, obng, obnb, out);
}

// round 4
// speedup vs baseline: 1.3783x; 1.1084x over previous
#include <cuda_runtime.h>

#define NPTS 100000
#define PCH  96
#define DIMC 192
#define KTAP 27

// ---------------- scratch (static device globals; no allocation) ------------
__device__ float g_v1[NPTS * PCH];
__device__ float g_v2[NPTS * DIMC];
__device__ float g_choice[NPTS * 24];
__device__ float g_agg[NPTS * DIMC];

// ---------------- sparse-pattern masks --------------------------------------
__constant__ int c_mask_items[3][4][9] = {
  { {0,1,3,6,7,13,-1,-1,-1}, {1,2,9,14,15,17,-1,-1,-1},
    {0,5,6,7,8,10,-1,-1,-1}, {17,19,20,22,23,-1,-1,-1,-1} },
  { {10,11,12,20,21,22,-1,-1,-1}, {1,2,3,4,5,6,10,21,20},
    {3,4,5,6,7,8,9,10,11},        {17,18,19,20,22,23,24,-1,-1} },
  { {0,5,9,13,19,22,-1,-1,-1}, {1,3,7,8,11,16,20,-1,-1},
    {4,6,11,12,18,24,25,-1,-1}, {5,6,10,14,19,23,-1,-1,-1} },
};
__constant__ int c_mask_len[3][4] = {{6,6,6,5},{6,9,9,7},{6,7,7,6}};

// ---------------- tf32 mma.sync + cp.async helpers ---------------------------
__device__ __forceinline__ void mma16818(float* d, const unsigned* a,
                                         const unsigned* b) {
  asm volatile(
    "mma.sync.aligned.m16n8k8.row.col.f32.tf32.tf32.f32 "
    "{%0,%1,%2,%3}, {%4,%5,%6,%7}, {%8,%9}, {%0,%1,%2,%3};"
    : "+f"(d[0]), "+f"(d[1]), "+f"(d[2]), "+f"(d[3])
    : "r"(a[0]), "r"(a[1]), "r"(a[2]), "r"(a[3]), "r"(b[0]), "r"(b[1]));
}
__device__ __forceinline__ void cpa16(float* dst, const float* src) {
  unsigned d = (unsigned)__cvta_generic_to_shared(dst);
  asm volatile("cp.async.ca.shared.global [%0], [%1], 16;" :: "r"(d), "l"(src));
}
__device__ __forceinline__ void cpa16z(float* dst, const float* src, int sz) {
  unsigned d = (unsigned)__cvta_generic_to_shared(dst);
  asm volatile("cp.async.ca.shared.global [%0], [%1], 16, %2;"
               :: "r"(d), "l"(src), "r"(sz));
}
#define CPA_COMMIT() asm volatile("cp.async.commit_group;" ::: "memory")
#define CPA_WAIT1()  asm volatile("cp.async.wait_group 1;" ::: "memory")
#define CPA_WAIT0()  asm volatile("cp.async.wait_group 0;" ::: "memory")

// =============================================================================
// K1 (tf32 + cp.async 2-stage): v1 = relu(BN( sum_k gather(x,neis[1]) @ W[k] ))
// Block 128x96, 8 warps = 4(M)x2(N), warp 32x48. A [128][100], B [96][104].
// =============================================================================
#define K1_APAD 100
#define K1_BPAD 104
#define K1_AS (128 * K1_APAD)
#define K1_BS (96 * K1_BPAD)
#define K1_STG (K1_AS + K1_BS)
#define K1_SMEM (2 * K1_STG * 4)   // 182272 bytes

__device__ __forceinline__ void k1_issue(
    float* stg, const float* __restrict__ x, const float* __restrict__ w,
    const int* __restrict__ neis, int k, int n0, int tid)
{
  const int arow = tid >> 1, ahalf = tid & 1;
  int n = n0 + arow;
  int nr = (n < NPTS) ? __ldg(&neis[(KTAP + k) * NPTS + n]) : NPTS;
  int sz = (nr < NPTS) ? 16 : 0;
  const float* srcA = x + (size_t)(nr < NPTS ? nr : 0) * PCH + ahalf * 48;
  float* dstA = stg + arow * K1_APAD + ahalf * 48;
  #pragma unroll
  for (int i = 0; i < 12; ++i) cpa16z(dstA + i * 4, srcA + i * 4, sz);
  const float* srcB = w + k * PCH * PCH;
  float* Bs = stg + K1_AS;
  #pragma unroll
  for (int j = 0; j < 9; ++j) {
    int idx = tid + j * 256;            // 2304 float4
    int row = idx / 24, q = idx % 24;
    cpa16(Bs + row * K1_BPAD + q * 4, srcB + idx * 4);
  }
}

__global__ __launch_bounds__(256) void k1_mma(
    const float* __restrict__ x, const int* __restrict__ neis,
    const float* __restrict__ w, const float* __restrict__ bng,
    const float* __restrict__ bnb)
{
  extern __shared__ float sm[];
  const int tid  = threadIdx.x;
  const int lane = tid & 31;
  const int wid  = tid >> 5;
  const int wm   = wid & 3;
  const int wn   = wid >> 2;
  const int n0   = blockIdx.x * 128;

  float d[2][6][4] = {};

  k1_issue(sm, x, w, neis, 0, n0, tid);
  CPA_COMMIT();

  for (int k = 0; k < KTAP; ++k) {
    if (k + 1 < KTAP) {
      k1_issue(sm + ((k + 1) & 1) * K1_STG, x, w, neis, k + 1, n0, tid);
      CPA_COMMIT();
      CPA_WAIT1();
    } else {
      CPA_WAIT0();
    }
    __syncthreads();
    const float* As = sm + (k & 1) * K1_STG;
    const float* Bs = As + K1_AS;
    #pragma unroll 2
    for (int ks = 0; ks < 12; ++ks) {
      unsigned a[2][4];
      {
        int c = ks * 8 + (lane & 3);
        #pragma unroll
        for (int mi = 0; mi < 2; ++mi) {
          int r = wm * 32 + mi * 16 + (lane >> 2);
          a[mi][0] = __float_as_uint(As[r * K1_APAD + c]);
          a[mi][1] = __float_as_uint(As[(r + 8) * K1_APAD + c]);
          a[mi][2] = __float_as_uint(As[r * K1_APAD + c + 4]);
          a[mi][3] = __float_as_uint(As[(r + 8) * K1_APAD + c + 4]);
        }
      }
      unsigned bf[6][2];
      {
        int br = ks * 8 + (lane & 3);
        int bc = wn * 48 + (lane >> 2);
        #pragma unroll
        for (int ni = 0; ni < 6; ++ni) {
          bf[ni][0] = __float_as_uint(Bs[br * K1_BPAD + bc + ni * 8]);
          bf[ni][1] = __float_as_uint(Bs[(br + 4) * K1_BPAD + bc + ni * 8]);
        }
      }
      #pragma unroll
      for (int mi = 0; mi < 2; ++mi)
        #pragma unroll
        for (int ni = 0; ni < 6; ++ni)
          mma16818(d[mi][ni], a[mi], bf[ni]);
    }
    __syncthreads();
  }

  #pragma unroll
  for (int mi = 0; mi < 2; ++mi) {
    int r0 = n0 + wm * 32 + mi * 16 + (lane >> 2);
    #pragma unroll
    for (int ni = 0; ni < 6; ++ni) {
      int c = wn * 48 + ni * 8 + (lane & 3) * 2;
      float g0 = __ldg(&bng[c]),     b0 = __ldg(&bnb[c]);
      float g1 = __ldg(&bng[c + 1]), b1 = __ldg(&bnb[c + 1]);
      if (r0 < NPTS) {
        float2 v;
        v.x = fmaxf(fmaf(d[mi][ni][0], g0, b0), 0.f);
        v.y = fmaxf(fmaf(d[mi][ni][1], g1, b1), 0.f);
        *(float2*)&g_v1[(size_t)r0 * PCH + c] = v;
      }
      if (r0 + 8 < NPTS) {
        float2 v;
        v.x = fmaxf(fmaf(d[mi][ni][2], g0, b0), 0.f);
        v.y = fmaxf(fmaf(d[mi][ni][3], g1, b1), 0.f);
        *(float2*)&g_v1[(size_t)(r0 + 8) * PCH + c] = v;
      }
    }
  }
}

// =============================================================================
// K2: v2 = relu( (v1 @ w_v2) * bn2_g + bn2_b )   [100k,96]@[96,192]
// =============================================================================
__global__ __launch_bounds__(256) void k2_fc_v2(
    const float* __restrict__ w2, const float* __restrict__ bng,
    const float* __restrict__ bnb)
{
  extern __shared__ float sm[];
  float* vs = sm;           // [64][100]
  float* ws = sm + 6400;    // [96][192]
  const int tid = threadIdx.x;
  const int n0  = blockIdx.x * 64;

  #pragma unroll
  for (int i = 0; i < 18; ++i)
    ((float4*)ws)[tid + i*256] = ((const float4*)w2)[tid + i*256];
  {
    int gp = tid >> 2, gq = tid & 3;
    int n = n0 + gp;
    float4 z = make_float4(0.f,0.f,0.f,0.f);
    #pragma unroll
    for (int t = 0; t < 6; ++t) {
      float4 v = z;
      if (n < NPTS) v = *(const float4*)(g_v1 + n*PCH + gq*24 + t*4);
      *(float4*)&vs[gp*100 + gq*24 + t*4] = v;
    }
  }
  __syncthreads();

  const int cg = tid & 15, pg = tid >> 4;
  float acc[4][12] = {};
  #pragma unroll 2
  for (int c = 0; c < PCH; ++c) {
    float xv[4];
    #pragma unroll
    for (int pp = 0; pp < 4; ++pp) xv[pp] = vs[(pg*4+pp)*100 + c];
    float wv[12];
    #pragma unroll
    for (int q = 0; q < 3; ++q) {
      float4 f = *(const float4*)&ws[c*DIMC + cg*12 + q*4];
      wv[q*4+0]=f.x; wv[q*4+1]=f.y; wv[q*4+2]=f.z; wv[q*4+3]=f.w;
    }
    #pragma unroll
    for (int pp = 0; pp < 4; ++pp)
      #pragma unroll
      for (int jj = 0; jj < 12; ++jj)
        acc[pp][jj] = fmaf(xv[pp], wv[jj], acc[pp][jj]);
  }
  #pragma unroll
  for (int pp = 0; pp < 4; ++pp) {
    int n = n0 + pg*4 + pp;
    if (n < NPTS) {
      #pragma unroll
      for (int jj = 0; jj < 12; ++jj) {
        int j = cg*12 + jj;
        g_v2[n*DIMC + j] = fmaxf(fmaf(acc[pp][jj], bng[j], bnb[j]), 0.f);
      }
    }
  }
}

// =============================================================================
// K3 (tf32 + cp.async 2-stage): query convs -> choice weights
// 128 points/block, 8 warps x 16 rows; N=8 per dilation, one mma per k-step.
// A [128][100] (as k1); B = qw tap [96][8] (K-major x N, stride 8 conflict-free)
// =============================================================================
#define K3_AS (128 * K1_APAD)
#define K3_BS (96 * 8)
#define K3_STG (K3_AS + K3_BS)
#define K3_SMEM (2 * K3_STG * 4)   // 108544 bytes

__device__ __forceinline__ void k3_issue(
    float* stg, const float* __restrict__ x, const float* __restrict__ qw,
    const int* __restrict__ neis, int t, int n0, int tid)
{
  const int arow = tid >> 1, ahalf = tid & 1;
  int n = n0 + arow;
  int nr = (n < NPTS) ? __ldg(&neis[t * NPTS + n]) : NPTS;
  int sz = (nr < NPTS) ? 16 : 0;
  const float* srcA = x + (size_t)(nr < NPTS ? nr : 0) * PCH + ahalf * 48;
  float* dstA = stg + arow * K1_APAD + ahalf * 48;
  #pragma unroll
  for (int i = 0; i < 12; ++i) cpa16z(dstA + i * 4, srcA + i * 4, sz);
  if (tid < 192)
    cpa16(stg + K3_AS + tid * 4, qw + t * (PCH * 8) + tid * 4);
}

__global__ __launch_bounds__(256) void k3_choice(
    const float* __restrict__ x, const int* __restrict__ neis,
    const float* __restrict__ qw)
{
  extern __shared__ float sm[];
  const int tid  = threadIdx.x;
  const int lane = tid & 31;
  const int wid  = tid >> 5;
  const int n0   = blockIdx.x * 128;

  float acc[3][4] = {};

  k3_issue(sm, x, qw, neis, 0, n0, tid);
  CPA_COMMIT();

  for (int t = 0; t < 3 * KTAP; ++t) {
    if (t + 1 < 3 * KTAP) {
      k3_issue(sm + ((t + 1) & 1) * K3_STG, x, qw, neis, t + 1, n0, tid);
      CPA_COMMIT();
      CPA_WAIT1();
    } else {
      CPA_WAIT0();
    }
    __syncthreads();
    const float* As = sm + (t & 1) * K3_STG;
    const float* Bs = As + K3_AS;
    const int dd = t / KTAP;
    const int r  = wid * 16 + (lane >> 2);
    #pragma unroll 3
    for (int ks = 0; ks < 12; ++ks) {
      unsigned a[4];
      int c = ks * 8 + (lane & 3);
      a[0] = __float_as_uint(As[r * K1_APAD + c]);
      a[1] = __float_as_uint(As[(r + 8) * K1_APAD + c]);
      a[2] = __float_as_uint(As[r * K1_APAD + c + 4]);
      a[3] = __float_as_uint(As[(r + 8) * K1_APAD + c + 4]);
      unsigned bf[2];
      int br = ks * 8 + (lane & 3), bc = lane >> 2;
      bf[0] = __float_as_uint(Bs[br * 8 + bc]);
      bf[1] = __float_as_uint(Bs[(br + 4) * 8 + bc]);
      mma16818(acc[dd], a, bf);
    }
    __syncthreads();
  }

  // dump logits to smem (overlay on stage 0; all reads done)
  float* qsm = sm;   // [128][25]
  {
    int r = wid * 16 + (lane >> 2);
    int c2 = (lane & 3) * 2;
    #pragma unroll
    for (int d = 0; d < 3; ++d) {
      qsm[r * 25 + d * 8 + c2]           = acc[d][0];
      qsm[r * 25 + d * 8 + c2 + 1]       = acc[d][1];
      qsm[(r + 8) * 25 + d * 8 + c2]     = acc[d][2];
      qsm[(r + 8) * 25 + d * 8 + c2 + 1] = acc[d][3];
    }
  }
  __syncthreads();

  if (tid < 128) {
    int n = n0 + tid;
    if (n < NPTS) {
      float t1[3][8];
      #pragma unroll
      for (int d = 0; d < 3; ++d) {
        unsigned pb = 0;
        #pragma unroll 1
        for (int k = 0; k < KTAP; ++k)
          pb |= (unsigned)(neis[(d*KTAP + k)*NPTS + n] < NPTS) << k;
        float v[8];
        #pragma unroll
        for (int mi = 0; mi < 4; ++mi) {
          unsigned ex = 0;
          #pragma unroll
          for (int tt = 0; tt < 9; ++tt) {
            int it = c_mask_items[d][mi][tt];
            if (it >= 0) ex |= (1u << it);
          }
          float keepinv = 1.f / (float)(27 - c_mask_len[d][mi]);
          float spv = (float)__popc(pb & ~ex & 0x7FFFFFFu) * keepinv;
          v[mi] = (spv + 1e-3f) * 5.f;
        }
        #pragma unroll
        for (int mi = 4; mi < 8; ++mi) v[mi] = 5e-3f;
        float mx = v[0];
        #pragma unroll
        for (int m = 1; m < 8; ++m) mx = fmaxf(mx, v[m]);
        float s = 0.f;
        #pragma unroll
        for (int m = 0; m < 8; ++m) { v[m] = __expf(v[m] - mx); s += v[m]; }
        float inv = 1.f / s;
        #pragma unroll
        for (int m = 0; m < 8; ++m) t1[d][m] = v[m] * inv;
      }
      #pragma unroll
      for (int m = 0; m < 8; ++m) {
        float a0 = (t1[0][m] + 1e-3f) * 5.f;
        float a1 = (t1[1][m] + 1e-3f) * 5.f;
        float a2 = (t1[2][m] + 1e-3f) * 5.f;
        float mx = fmaxf(a0, fmaxf(a1, a2));
        float e0 = __expf(a0 - mx), e1 = __expf(a1 - mx), e2 = __expf(a2 - mx);
        float inv = 1.f / (e0 + e1 + e2);
        t1[0][m] = e0 * inv; t1[1][m] = e1 * inv; t1[2][m] = e2 * inv;
      }
      #pragma unroll
      for (int d = 0; d < 3; ++d) {
        float sv[8];
        float mx = -1e30f;
        #pragma unroll
        for (int m = 0; m < 8; ++m) {
          sv[m] = qsm[tid*25 + d*8 + m] * 0.70710678118654752f;
          mx = fmaxf(mx, sv[m]);
        }
        float s = 0.f;
        #pragma unroll
        for (int m = 0; m < 8; ++m) { sv[m] = __expf(sv[m] - mx); s += sv[m]; }
        float inv = 1.f / s;
        #pragma unroll
        for (int m = 0; m < 8; ++m)
          g_choice[n*24 + d*8 + m] = sv[m] * inv * t1[d][m];
      }
    }
  }
}

// =============================================================================
// K4: agg[n,c] = sum_d choice[n,d,c/24] * sum_k cb_kern[d,k,c] * v2[neis[d,k,n],c]
// =============================================================================
__global__ __launch_bounds__(256) void k4_agg(
    const int* __restrict__ neis, const float* __restrict__ cb)
{
  extern __shared__ float ks[];   // 3*27*192 = 15552 floats
  for (int i = threadIdx.x; i < 3888; i += 256)
    ((float4*)ks)[i] = ((const float4*)cb)[i];
  __syncthreads();

  const int lane = threadIdx.x & 31;
  const int w    = threadIdx.x >> 5;
  const int n0   = blockIdx.x * 128 + w * 16;

  for (int pi = 0; pi < 16; ++pi) {
    int n = n0 + pi;
    if (n >= NPTS) break;
    float agg[6] = {0.f,0.f,0.f,0.f,0.f,0.f};
    #pragma unroll
    for (int d = 0; d < 3; ++d) {
      float pd[6] = {0.f,0.f,0.f,0.f,0.f,0.f};
      const int* nd = neis + d*KTAP*NPTS + n;
      #pragma unroll 1
      for (int k = 0; k < KTAP; ++k) {
        int r = nd[k*NPTS];
        if (r < NPTS) {
          const float* vr = g_v2 + r*DIMC + lane;
          const float* kk = ks + (d*KTAP + k)*DIMC + lane;
          #pragma unroll
          for (int i = 0; i < 6; ++i)
            pd[i] = fmaf(kk[32*i], vr[32*i], pd[i]);
        }
      }
      #pragma unroll
      for (int i = 0; i < 6; ++i) {
        int c = lane + 32*i;
        agg[i] += pd[i] * g_choice[n*24 + d*8 + (c/24)];
      }
    }
    #pragma unroll
    for (int i = 0; i < 6; ++i)
      g_agg[n*DIMC + lane + 32*i] = agg[i];
  }
}

// =============================================================================
// K5: out = relu( (agg @ out_w) * out_bn_g + out_bn_b ) + x
// =============================================================================
__global__ __launch_bounds__(256) void k5_out(
    const float* __restrict__ x, const float* __restrict__ ow,
    const float* __restrict__ bng, const float* __restrict__ bnb,
    float* __restrict__ out)
{
  extern __shared__ float sm[];
  float* vs = sm;          // [64][100]
  float* ws = sm + 6400;   // [96][96]
  const int tid = threadIdx.x;
  const int n0  = blockIdx.x * 64;
  const int cg  = tid & 15, pg = tid >> 4;
  const int gp  = tid >> 2, gq = tid & 3;

  float acc[4][6] = {};
  for (int h = 0; h < 2; ++h) {
    #pragma unroll
    for (int i = 0; i < 9; ++i)
      ((float4*)ws)[tid + i*256] = ((const float4*)(ow + h*9216))[tid + i*256];
    {
      int n = n0 + gp;
      float4 z = make_float4(0.f,0.f,0.f,0.f);
      #pragma unroll
      for (int t = 0; t < 6; ++t) {
        float4 v = z;
        if (n < NPTS) v = *(const float4*)(g_agg + n*DIMC + h*96 + gq*24 + t*4);
        *(float4*)&vs[gp*100 + gq*24 + t*4] = v;
      }
    }
    __syncthreads();
    #pragma unroll 2
    for (int c = 0; c < PCH; ++c) {
      float xv[4];
      #pragma unroll
      for (int pp = 0; pp < 4; ++pp) xv[pp] = vs[(pg*4+pp)*100 + c];
      float wv[6];
      #pragma unroll
      for (int q = 0; q < 3; ++q) {
        float2 f = *(const float2*)&ws[c*PCH + cg*6 + q*2];
        wv[q*2] = f.x; wv[q*2+1] = f.y;
      }
      #pragma unroll
      for (int pp = 0; pp < 4; ++pp)
        #pragma unroll
        for (int jj = 0; jj < 6; ++jj)
          acc[pp][jj] = fmaf(xv[pp], wv[jj], acc[pp][jj]);
    }
    __syncthreads();
  }
  #pragma unroll
  for (int pp = 0; pp < 4; ++pp) {
    int n = n0 + pg*4 + pp;
    if (n < NPTS) {
      #pragma unroll
      for (int jj = 0; jj < 6; ++jj) {
        int j = cg*6 + jj;
        float v = fmaxf(fmaf(acc[pp][jj], bng[j], bnb[j]), 0.f);
        out[n*PCH + j] = v + x[n*PCH + j];
      }
    }
  }
}

// =============================================================================
extern "C" void kernel_launch(void* const* d_in, const int* in_sizes, int n_in,
                              void* d_out, int out_size)
{
  const float* x    = (const float*)d_in[0];
  const int*   neis = (const int*)  d_in[1];
  const float* w_v1 = (const float*)d_in[2];
  const float* bn1g = (const float*)d_in[3];
  const float* bn1b = (const float*)d_in[4];
  const float* w_v2 = (const float*)d_in[5];
  const float* bn2g = (const float*)d_in[6];
  const float* bn2b = (const float*)d_in[7];
  const float* q_w  = (const float*)d_in[8];
  const float* cbk  = (const float*)d_in[9];
  const float* outw = (const float*)d_in[10];
  const float* obng = (const float*)d_in[11];
  const float* obnb = (const float*)d_in[12];
  float* out = (float*)d_out;

  const int SM2 = (6400 + 18432) * 4;   // 99328
  const int SM4 = 15552 * 4;            // 62208
  const int SM5 = (6400 + 9216)  * 4;   // 62464

  cudaFuncSetAttribute(k1_mma,   cudaFuncAttributeMaxDynamicSharedMemorySize, K1_SMEM);
  cudaFuncSetAttribute(k2_fc_v2, cudaFuncAttributeMaxDynamicSharedMemorySize, SM2);
  cudaFuncSetAttribute(k3_choice,cudaFuncAttributeMaxDynamicSharedMemorySize, K3_SMEM);
  cudaFuncSetAttribute(k4_agg,   cudaFuncAttributeMaxDynamicSharedMemorySize, SM4);
  cudaFuncSetAttribute(k5_out,   cudaFuncAttributeMaxDynamicSharedMemorySize, SM5);

  k1_mma    <<<(NPTS + 127) / 128, 256, K1_SMEM>>>(x, neis, w_v1, bn1g, bn1b);
  k2_fc_v2  <<<(NPTS + 63) / 64,   256, SM2>>>(w_v2, bn2g, bn2b);
  k3_choice <<<(NPTS + 127) / 128, 256, K3_SMEM>>>(x, neis, q_w);
  k4_agg    <<<(NPTS + 127) / 128, 256, SM4>>>(neis, cbk);
  k5_out    <<<(NPTS + 63) / 64,   256, SM5>>>(x, outw, obng, obnb, out);
}

// round 5
// speedup vs baseline: 2.5570x; 1.8552x over previous
#include <cuda_runtime.h>
#include <cuda_fp16.h>

#define NPTS 100000
#define PCH  96
#define DIMC 192
#define KTAP 27

// ---------------- scratch (static device globals; no allocation) ------------
__device__ float  g_v1[NPTS * PCH];           // value branch fp32
__device__ __half g_v2h[NPTS * DIMC];         // v2 in fp16 (k4 gather)
__device__ float  g_choice[NPTS * 24];
__device__ float  g_agg[NPTS * DIMC];
__device__ __half g_xh[NPTS * PCH];           // x in fp16
__device__ __half g_wh1[KTAP * PCH * PCH];    // w_v1 fp16, [k][n][c]
__device__ __half g_qwh[3 * KTAP * 8 * PCH];  // q_w fp16,  [t][n=8][c=96]

// ---------------- sparse-pattern masks --------------------------------------
__constant__ int c_mask_items[3][4][9] = {
  { {0,1,3,6,7,13,-1,-1,-1}, {1,2,9,14,15,17,-1,-1,-1},
    {0,5,6,7,8,10,-1,-1,-1}, {17,19,20,22,23,-1,-1,-1,-1} },
  { {10,11,12,20,21,22,-1,-1,-1}, {1,2,3,4,5,6,10,21,20},
    {3,4,5,6,7,8,9,10,11},        {17,18,19,20,22,23,24,-1,-1} },
  { {0,5,9,13,19,22,-1,-1,-1}, {1,3,7,8,11,16,20,-1,-1},
    {4,6,11,12,18,24,25,-1,-1}, {5,6,10,14,19,23,-1,-1,-1} },
};
__constant__ int c_mask_len[3][4] = {{6,6,6,5},{6,9,9,7},{6,7,7,6}};

// ---------------- mma + cp.async helpers -------------------------------------
__device__ __forceinline__ void mma_f16(float* d, const unsigned* a,
                                        const unsigned* b) {
  asm volatile(
    "mma.sync.aligned.m16n8k16.row.col.f32.f16.f16.f32 "
    "{%0,%1,%2,%3}, {%4,%5,%6,%7}, {%8,%9}, {%0,%1,%2,%3};"
    : "+f"(d[0]), "+f"(d[1]), "+f"(d[2]), "+f"(d[3])
    : "r"(a[0]), "r"(a[1]), "r"(a[2]), "r"(a[3]), "r"(b[0]), "r"(b[1]));
}
__device__ __forceinline__ void cpa16(void* dst, const void* src) {
  unsigned d = (unsigned)__cvta_generic_to_shared(dst);
  asm volatile("cp.async.ca.shared.global [%0], [%1], 16;" :: "r"(d), "l"(src));
}
__device__ __forceinline__ void cpa16z(void* dst, const void* src, int sz) {
  unsigned d = (unsigned)__cvta_generic_to_shared(dst);
  asm volatile("cp.async.ca.shared.global [%0], [%1], 16, %2;"
               :: "r"(d), "l"(src), "r"(sz));
}
#define CPA_COMMIT() asm volatile("cp.async.commit_group;" ::: "memory")
#define CPA_WAIT1()  asm volatile("cp.async.wait_group 1;" ::: "memory")
#define CPA_WAIT0()  asm volatile("cp.async.wait_group 0;" ::: "memory")

// =============================================================================
// K0: one-shot fp16 conversions (deterministic every call)
// =============================================================================
__global__ __launch_bounds__(256) void k0_cvt_x(const float* __restrict__ x) {
  int i = blockIdx.x * 256 + threadIdx.x;
  int stride = gridDim.x * 256;
  for (; i < NPTS * PCH; i += stride) g_xh[i] = __float2half(x[i]);
}
__global__ __launch_bounds__(256) void k0_cvt_w1(const float* __restrict__ w) {
  int k = blockIdx.x;
  const float* src = w + k * PCH * PCH;     // [c][n]
  __half* dst = g_wh1 + k * PCH * PCH;      // [n][c]
  for (int i = threadIdx.x; i < PCH * PCH; i += 256) {
    int n = i / PCH, c = i % PCH;
    dst[i] = __float2half(src[c * PCH + n]);
  }
}
__global__ __launch_bounds__(256) void k0_cvt_qw(const float* __restrict__ qw) {
  int t = blockIdx.x;                        // 0..80
  const float* src = qw + t * (PCH * 8);     // [c][n=8]
  __half* dst = g_qwh + t * (8 * PCH);       // [n][c]
  for (int i = threadIdx.x; i < 8 * PCH; i += 256) {
    int n = i / PCH, c = i % PCH;
    dst[i] = __float2half(src[c * 8 + n]);
  }
}

// =============================================================================
// K1 (fp16 mma + cp.async 2-stage): v1 = relu(BN( sum_k gather @ W[k] ))
// Block 128x96, 8 warps = 4(M)x2(N), warp 32x48. A [128][104]h, B [96][104]h.
// =============================================================================
#define K1_APAD 104
#define K1_AS (128 * K1_APAD)                 // halfs
#define K1_BS (96 * K1_APAD)
#define K1_STG (K1_AS + K1_BS)
#define K1_SMEM (2 * K1_STG * 2)              // 93184 bytes

__device__ __forceinline__ void k1_issue(
    __half* stg, const int* __restrict__ neis, int k, int n0, int tid)
{
  const int arow = tid >> 1, ahalf = tid & 1;
  int n = n0 + arow;
  int nr = (n < NPTS) ? __ldg(&neis[(KTAP + k) * NPTS + n]) : NPTS;
  int sz = (nr < NPTS) ? 16 : 0;
  const __half* srcA = g_xh + (size_t)(nr < NPTS ? nr : 0) * PCH + ahalf * 48;
  __half* dstA = stg + arow * K1_APAD + ahalf * 48;
  #pragma unroll
  for (int i = 0; i < 6; ++i) cpa16z(dstA + i * 8, srcA + i * 8, sz);
  const __half* srcB = g_wh1 + k * PCH * PCH;       // [n][c]
  __half* Bs = stg + K1_AS;
  #pragma unroll
  for (int j = 0; j < 5; ++j) {
    int idx = tid + j * 256;                  // 1152 16B-chunks (96 rows x 12)
    if (idx < 1152) {
      int row = idx / 12, q = idx % 12;
      cpa16(Bs + row * K1_APAD + q * 8, srcB + row * PCH + q * 8);
    }
  }
}

__global__ __launch_bounds__(256) void k1_mma(
    const int* __restrict__ neis, const float* __restrict__ bng,
    const float* __restrict__ bnb)
{
  extern __shared__ char smem8[];
  __half* sm = (__half*)smem8;
  const int tid  = threadIdx.x;
  const int lane = tid & 31;
  const int wid  = tid >> 5;
  const int wm   = wid & 3;
  const int wn   = wid >> 2;
  const int n0   = blockIdx.x * 128;

  float d[2][6][4] = {};

  k1_issue(sm, neis, 0, n0, tid);
  CPA_COMMIT();

  for (int k = 0; k < KTAP; ++k) {
    if (k + 1 < KTAP) {
      k1_issue(sm + ((k + 1) & 1) * K1_STG, neis, k + 1, n0, tid);
      CPA_COMMIT();
      CPA_WAIT1();
    } else {
      CPA_WAIT0();
    }
    __syncthreads();
    const __half* As = sm + (k & 1) * K1_STG;
    const __half* Bs = As + K1_AS;
    #pragma unroll
    for (int ks = 0; ks < 6; ++ks) {
      unsigned a[2][4];
      {
        int c0 = ks * 16 + (lane & 3) * 2;
        #pragma unroll
        for (int mi = 0; mi < 2; ++mi) {
          int r = wm * 32 + mi * 16 + (lane >> 2);
          a[mi][0] = *(const unsigned*)&As[r * K1_APAD + c0];
          a[mi][1] = *(const unsigned*)&As[(r + 8) * K1_APAD + c0];
          a[mi][2] = *(const unsigned*)&As[r * K1_APAD + c0 + 8];
          a[mi][3] = *(const unsigned*)&As[(r + 8) * K1_APAD + c0 + 8];
        }
      }
      unsigned bf[6][2];
      {
        int kk = ks * 16 + (lane & 3) * 2;
        #pragma unroll
        for (int ni = 0; ni < 6; ++ni) {
          int n = wn * 48 + ni * 8 + (lane >> 2);
          bf[ni][0] = *(const unsigned*)&Bs[n * K1_APAD + kk];
          bf[ni][1] = *(const unsigned*)&Bs[n * K1_APAD + kk + 8];
        }
      }
      #pragma unroll
      for (int mi = 0; mi < 2; ++mi)
        #pragma unroll
        for (int ni = 0; ni < 6; ++ni)
          mma_f16(d[mi][ni], a[mi], bf[ni]);
    }
    __syncthreads();
  }

  #pragma unroll
  for (int mi = 0; mi < 2; ++mi) {
    int r0 = n0 + wm * 32 + mi * 16 + (lane >> 2);
    #pragma unroll
    for (int ni = 0; ni < 6; ++ni) {
      int c = wn * 48 + ni * 8 + (lane & 3) * 2;
      float g0 = __ldg(&bng[c]),     b0 = __ldg(&bnb[c]);
      float g1 = __ldg(&bng[c + 1]), b1 = __ldg(&bnb[c + 1]);
      if (r0 < NPTS) {
        float2 v;
        v.x = fmaxf(fmaf(d[mi][ni][0], g0, b0), 0.f);
        v.y = fmaxf(fmaf(d[mi][ni][1], g1, b1), 0.f);
        *(float2*)&g_v1[(size_t)r0 * PCH + c] = v;
      }
      if (r0 + 8 < NPTS) {
        float2 v;
        v.x = fmaxf(fmaf(d[mi][ni][2], g0, b0), 0.f);
        v.y = fmaxf(fmaf(d[mi][ni][3], g1, b1), 0.f);
        *(float2*)&g_v1[(size_t)(r0 + 8) * PCH + c] = v;
      }
    }
  }
}

// =============================================================================
// K2: v2h = fp16(relu( (v1 @ w_v2) * bn2_g + bn2_b ))
// =============================================================================
__global__ __launch_bounds__(256) void k2_fc_v2(
    const float* __restrict__ w2, const float* __restrict__ bng,
    const float* __restrict__ bnb)
{
  extern __shared__ float sm[];
  float* vs = sm;           // [64][100]
  float* ws = sm + 6400;    // [96][192]
  const int tid = threadIdx.x;
  const int n0  = blockIdx.x * 64;

  #pragma unroll
  for (int i = 0; i < 18; ++i)
    ((float4*)ws)[tid + i*256] = ((const float4*)w2)[tid + i*256];
  {
    int gp = tid >> 2, gq = tid & 3;
    int n = n0 + gp;
    float4 z = make_float4(0.f,0.f,0.f,0.f);
    #pragma unroll
    for (int t = 0; t < 6; ++t) {
      float4 v = z;
      if (n < NPTS) v = *(const float4*)(g_v1 + n*PCH + gq*24 + t*4);
      *(float4*)&vs[gp*100 + gq*24 + t*4] = v;
    }
  }
  __syncthreads();

  const int cg = tid & 15, pg = tid >> 4;
  float acc[4][12] = {};
  #pragma unroll 2
  for (int c = 0; c < PCH; ++c) {
    float xv[4];
    #pragma unroll
    for (int pp = 0; pp < 4; ++pp) xv[pp] = vs[(pg*4+pp)*100 + c];
    float wv[12];
    #pragma unroll
    for (int q = 0; q < 3; ++q) {
      float4 f = *(const float4*)&ws[c*DIMC + cg*12 + q*4];
      wv[q*4+0]=f.x; wv[q*4+1]=f.y; wv[q*4+2]=f.z; wv[q*4+3]=f.w;
    }
    #pragma unroll
    for (int pp = 0; pp < 4; ++pp)
      #pragma unroll
      for (int jj = 0; jj < 12; ++jj)
        acc[pp][jj] = fmaf(xv[pp], wv[jj], acc[pp][jj]);
  }
  #pragma unroll
  for (int pp = 0; pp < 4; ++pp) {
    int n = n0 + pg*4 + pp;
    if (n < NPTS) {
      #pragma unroll
      for (int jj = 0; jj < 12; jj += 2) {
        int j = cg*12 + jj;
        float v0 = fmaxf(fmaf(acc[pp][jj],   bng[j],   bnb[j]),   0.f);
        float v1 = fmaxf(fmaf(acc[pp][jj+1], bng[j+1], bnb[j+1]), 0.f);
        *(__half2*)&g_v2h[n*DIMC + j] = __floats2half2_rn(v0, v1);
      }
    }
  }
}

// =============================================================================
// K3 (fp16 mma + cp.async 2-stage): query convs -> choice weights
// A [128][104]h; B tap [8][104]h. 1 mma per k16-step, 6 steps/tap, 81 taps.
// =============================================================================
#define K3_AS (128 * K1_APAD)
#define K3_BS (8 * K1_APAD)
#define K3_STG (K3_AS + K3_BS)
#define K3_SMEM (2 * K3_STG * 2)              // 56576 bytes

__device__ __forceinline__ void k3_issue(
    __half* stg, const int* __restrict__ neis, int t, int n0, int tid)
{
  const int arow = tid >> 1, ahalf = tid & 1;
  int n = n0 + arow;
  int nr = (n < NPTS) ? __ldg(&neis[t * NPTS + n]) : NPTS;
  int sz = (nr < NPTS) ? 16 : 0;
  const __half* srcA = g_xh + (size_t)(nr < NPTS ? nr : 0) * PCH + ahalf * 48;
  __half* dstA = stg + arow * K1_APAD + ahalf * 48;
  #pragma unroll
  for (int i = 0; i < 6; ++i) cpa16z(dstA + i * 8, srcA + i * 8, sz);
  if (tid < 96) {
    int row = tid / 12, q = tid % 12;         // 8 rows x 12 chunks
    cpa16(stg + K3_AS + row * K1_APAD + q * 8,
          g_qwh + t * (8 * PCH) + row * PCH + q * 8);
  }
}

__global__ __launch_bounds__(256) void k3_choice(
    const int* __restrict__ neis)
{
  extern __shared__ char smem8[];
  __half* sm = (__half*)smem8;
  const int tid  = threadIdx.x;
  const int lane = tid & 31;
  const int wid  = tid >> 5;
  const int n0   = blockIdx.x * 128;

  float acc[3][4] = {};

  k3_issue(sm, neis, 0, n0, tid);
  CPA_COMMIT();

  for (int t = 0; t < 3 * KTAP; ++t) {
    if (t + 1 < 3 * KTAP) {
      k3_issue(sm + ((t + 1) & 1) * K3_STG, neis, t + 1, n0, tid);
      CPA_COMMIT();
      CPA_WAIT1();
    } else {
      CPA_WAIT0();
    }
    __syncthreads();
    const __half* As = sm + (t & 1) * K3_STG;
    const __half* Bs = As + K3_AS;
    const int dd = t / KTAP;
    const int r  = wid * 16 + (lane >> 2);
    #pragma unroll
    for (int ks = 0; ks < 6; ++ks) {
      int c0 = ks * 16 + (lane & 3) * 2;
      unsigned a[4];
      a[0] = *(const unsigned*)&As[r * K1_APAD + c0];
      a[1] = *(const unsigned*)&As[(r + 8) * K1_APAD + c0];
      a[2] = *(const unsigned*)&As[r * K1_APAD + c0 + 8];
      a[3] = *(const unsigned*)&As[(r + 8) * K1_APAD + c0 + 8];
      unsigned bf[2];
      int n = lane >> 2;
      bf[0] = *(const unsigned*)&Bs[n * K1_APAD + c0];
      bf[1] = *(const unsigned*)&Bs[n * K1_APAD + c0 + 8];
      mma_f16(acc[dd], a, bf);
    }
    __syncthreads();
  }

  float* qsm = (float*)smem8;   // [128][25], overlays stage (reads done)
  {
    int r = wid * 16 + (lane >> 2);
    int c2 = (lane & 3) * 2;
    #pragma unroll
    for (int d = 0; d < 3; ++d) {
      qsm[r * 25 + d * 8 + c2]           = acc[d][0];
      qsm[r * 25 + d * 8 + c2 + 1]       = acc[d][1];
      qsm[(r + 8) * 25 + d * 8 + c2]     = acc[d][2];
      qsm[(r + 8) * 25 + d * 8 + c2 + 1] = acc[d][3];
    }
  }
  __syncthreads();

  if (tid < 128) {
    int n = n0 + tid;
    if (n < NPTS) {
      float t1[3][8];
      #pragma unroll
      for (int d = 0; d < 3; ++d) {
        unsigned pb = 0;
        #pragma unroll 1
        for (int k = 0; k < KTAP; ++k)
          pb |= (unsigned)(neis[(d*KTAP + k)*NPTS + n] < NPTS) << k;
        float v[8];
        #pragma unroll
        for (int mi = 0; mi < 4; ++mi) {
          unsigned ex = 0;
          #pragma unroll
          for (int tt = 0; tt < 9; ++tt) {
            int it = c_mask_items[d][mi][tt];
            if (it >= 0) ex |= (1u << it);
          }
          float keepinv = 1.f / (float)(27 - c_mask_len[d][mi]);
          float spv = (float)__popc(pb & ~ex & 0x7FFFFFFu) * keepinv;
          v[mi] = (spv + 1e-3f) * 5.f;
        }
        #pragma unroll
        for (int mi = 4; mi < 8; ++mi) v[mi] = 5e-3f;
        float mx = v[0];
        #pragma unroll
        for (int m = 1; m < 8; ++m) mx = fmaxf(mx, v[m]);
        float s = 0.f;
        #pragma unroll
        for (int m = 0; m < 8; ++m) { v[m] = __expf(v[m] - mx); s += v[m]; }
        float inv = 1.f / s;
        #pragma unroll
        for (int m = 0; m < 8; ++m) t1[d][m] = v[m] * inv;
      }
      #pragma unroll
      for (int m = 0; m < 8; ++m) {
        float a0 = (t1[0][m] + 1e-3f) * 5.f;
        float a1 = (t1[1][m] + 1e-3f) * 5.f;
        float a2 = (t1[2][m] + 1e-3f) * 5.f;
        float mx = fmaxf(a0, fmaxf(a1, a2));
        float e0 = __expf(a0 - mx), e1 = __expf(a1 - mx), e2 = __expf(a2 - mx);
        float inv = 1.f / (e0 + e1 + e2);
        t1[0][m] = e0 * inv; t1[1][m] = e1 * inv; t1[2][m] = e2 * inv;
      }
      #pragma unroll
      for (int d = 0; d < 3; ++d) {
        float sv[8];
        float mx = -1e30f;
        #pragma unroll
        for (int m = 0; m < 8; ++m) {
          sv[m] = qsm[tid*25 + d*8 + m] * 0.70710678118654752f;
          mx = fmaxf(mx, sv[m]);
        }
        float s = 0.f;
        #pragma unroll
        for (int m = 0; m < 8; ++m) { sv[m] = __expf(sv[m] - mx); s += sv[m]; }
        float inv = 1.f / s;
        #pragma unroll
        for (int m = 0; m < 8; ++m)
          g_choice[n*24 + d*8 + m] = sv[m] * inv * t1[d][m];
      }
    }
  }
}

// =============================================================================
// K4: agg[n,c] = sum_d choice[n,d,c/24] * sum_k cb[d,k,c] * v2h[neis[d,k,n],c]
// warp-per-point; lane handles half2 pairs c = lane*2 + 64*i (i<3)
// =============================================================================
__global__ __launch_bounds__(256) void k4_agg(
    const int* __restrict__ neis, const float* __restrict__ cb)
{
  extern __shared__ float ks[];   // 3*27*192 = 15552 floats
  for (int i = threadIdx.x; i < 3888; i += 256)
    ((float4*)ks)[i] = ((const float4*)cb)[i];
  __syncthreads();

  const int lane = threadIdx.x & 31;
  const int w    = threadIdx.x >> 5;
  const int n0   = blockIdx.x * 128 + w * 16;

  for (int pi = 0; pi < 16; ++pi) {
    int n = n0 + pi;
    if (n >= NPTS) break;
    float agg[6] = {0.f,0.f,0.f,0.f,0.f,0.f};
    #pragma unroll
    for (int d = 0; d < 3; ++d) {
      float pd[6] = {0.f,0.f,0.f,0.f,0.f,0.f};
      const int* nd = neis + d*KTAP*NPTS + n;
      #pragma unroll 1
      for (int k = 0; k < KTAP; ++k) {
        int r = nd[k*NPTS];
        if (r < NPTS) {
          const __half2* vr = (const __half2*)(g_v2h + (size_t)r * DIMC);
          const float* kk = ks + (d*KTAP + k)*DIMC;
          #pragma unroll
          for (int i = 0; i < 3; ++i) {
            float2 f = __half22float2(vr[lane + 32*i]);
            int c = lane*2 + 64*i;
            pd[2*i]   = fmaf(kk[c],   f.x, pd[2*i]);
            pd[2*i+1] = fmaf(kk[c+1], f.y, pd[2*i+1]);
          }
        }
      }
      #pragma unroll
      for (int i = 0; i < 3; ++i) {
        int c = lane*2 + 64*i;
        float ch = g_choice[n*24 + d*8 + (c/24)];   // pair shares group (24 even)
        agg[2*i]   += pd[2*i]   * ch;
        agg[2*i+1] += pd[2*i+1] * ch;
      }
    }
    #pragma unroll
    for (int i = 0; i < 3; ++i) {
      int c = lane*2 + 64*i;
      *(float2*)&g_agg[(size_t)n*DIMC + c] = make_float2(agg[2*i], agg[2*i+1]);
    }
  }
}

// =============================================================================
// K5: out = relu( (agg @ out_w) * out_bn_g + out_bn_b ) + x
// =============================================================================
__global__ __launch_bounds__(256) void k5_out(
    const float* __restrict__ x, const float* __restrict__ ow,
    const float* __restrict__ bng, const float* __restrict__ bnb,
    float* __restrict__ out)
{
  extern __shared__ float sm[];
  float* vs = sm;          // [64][100]
  float* ws = sm + 6400;   // [96][96]
  const int tid = threadIdx.x;
  const int n0  = blockIdx.x * 64;
  const int cg  = tid & 15, pg = tid >> 4;
  const int gp  = tid >> 2, gq = tid & 3;

  float acc[4][6] = {};
  for (int h = 0; h < 2; ++h) {
    #pragma unroll
    for (int i = 0; i < 9; ++i)
      ((float4*)ws)[tid + i*256] = ((const float4*)(ow + h*9216))[tid + i*256];
    {
      int n = n0 + gp;
      float4 z = make_float4(0.f,0.f,0.f,0.f);
      #pragma unroll
      for (int t = 0; t < 6; ++t) {
        float4 v = z;
        if (n < NPTS) v = *(const float4*)(g_agg + (size_t)n*DIMC + h*96 + gq*24 + t*4);
        *(float4*)&vs[gp*100 + gq*24 + t*4] = v;
      }
    }
    __syncthreads();
    #pragma unroll 2
    for (int c = 0; c < PCH; ++c) {
      float xv[4];
      #pragma unroll
      for (int pp = 0; pp < 4; ++pp) xv[pp] = vs[(pg*4+pp)*100 + c];
      float wv[6];
      #pragma unroll
      for (int q = 0; q < 3; ++q) {
        float2 f = *(const float2*)&ws[c*PCH + cg*6 + q*2];
        wv[q*2] = f.x; wv[q*2+1] = f.y;
      }
      #pragma unroll
      for (int pp = 0; pp < 4; ++pp)
        #pragma unroll
        for (int jj = 0; jj < 6; ++jj)
          acc[pp][jj] = fmaf(xv[pp], wv[jj], acc[pp][jj]);
    }
    __syncthreads();
  }
  #pragma unroll
  for (int pp = 0; pp < 4; ++pp) {
    int n = n0 + pg*4 + pp;
    if (n < NPTS) {
      #pragma unroll
      for (int jj = 0; jj < 6; ++jj) {
        int j = cg*6 + jj;
        float v = fmaxf(fmaf(acc[pp][jj], bng[j], bnb[j]), 0.f);
        out[n*PCH + j] = v + x[n*PCH + j];
      }
    }
  }
}

// =============================================================================
extern "C" void kernel_launch(void* const* d_in, const int* in_sizes, int n_in,
                              void* d_out, int out_size)
{
  const float* x    = (const float*)d_in[0];
  const int*   neis = (const int*)  d_in[1];
  const float* w_v1 = (const float*)d_in[2];
  const float* bn1g = (const float*)d_in[3];
  const float* bn1b = (const float*)d_in[4];
  const float* w_v2 = (const float*)d_in[5];
  const float* bn2g = (const float*)d_in[6];
  const float* bn2b = (const float*)d_in[7];
  const float* q_w  = (const float*)d_in[8];
  const float* cbk  = (const float*)d_in[9];
  const float* outw = (const float*)d_in[10];
  const float* obng = (const float*)d_in[11];
  const float* obnb = (const float*)d_in[12];
  float* out = (float*)d_out;

  const int SM2 = (6400 + 18432) * 4;   // 99328
  const int SM4 = 15552 * 4;            // 62208
  const int SM5 = (6400 + 9216)  * 4;   // 62464

  cudaFuncSetAttribute(k1_mma,   cudaFuncAttributeMaxDynamicSharedMemorySize, K1_SMEM);
  cudaFuncSetAttribute(k2_fc_v2, cudaFuncAttributeMaxDynamicSharedMemorySize, SM2);
  cudaFuncSetAttribute(k3_choice,cudaFuncAttributeMaxDynamicSharedMemorySize, K3_SMEM);
  cudaFuncSetAttribute(k4_agg,   cudaFuncAttributeMaxDynamicSharedMemorySize, SM4);
  cudaFuncSetAttribute(k5_out,   cudaFuncAttributeMaxDynamicSharedMemorySize, SM5);

  k0_cvt_x  <<<512, 256>>>(x);
  k0_cvt_w1 <<<KTAP, 256>>>(w_v1);
  k0_cvt_qw <<<3 * KTAP, 256>>>(q_w);

  k1_mma    <<<(NPTS + 127) / 128, 256, K1_SMEM>>>(neis, bn1g, bn1b);
  k2_fc_v2  <<<(NPTS + 63) / 64,   256, SM2>>>(w_v2, bn2g, bn2b);
  k3_choice <<<(NPTS + 127) / 128, 256, K3_SMEM>>>(neis);
  k4_agg    <<<(NPTS + 127) / 128, 256, SM4>>>(neis, cbk);
  k5_out    <<<(NPTS + 63) / 64,   256, SM5>>>(x, outw, obng, obnb, out);
}

// round 6
// speedup vs baseline: 2.9000x; 1.1341x over previous
#include <cuda_runtime.h>
#include <cuda_fp16.h>

#define NPTS 100000
#define PCH  96
#define DIMC 192
#define KTAP 27

// ---------------- scratch (static device globals; no allocation) ------------
__device__ __half g_v1h[NPTS * PCH];          // v1 fp16
__device__ __half g_v2h[NPTS * DIMC];         // v2 fp16
__device__ float  g_choice[NPTS * 24];
__device__ __half g_aggh[NPTS * DIMC];        // agg fp16
__device__ __half g_xh[NPTS * PCH];           // x fp16
__device__ __half g_wh1[KTAP * PCH * PCH];    // w_v1 fp16 [k][n][c]
__device__ __half g_qwh[3 * KTAP * 8 * PCH];  // q_w fp16  [t][n=8][c=96]
__device__ __half g_w2h[DIMC * PCH];          // w_v2 fp16 [j=192][c=96]
__device__ __half g_owh[PCH * DIMC];          // out_w fp16 [j=96][c=192]

// ---------------- sparse-pattern masks --------------------------------------
__constant__ int c_mask_items[3][4][9] = {
  { {0,1,3,6,7,13,-1,-1,-1}, {1,2,9,14,15,17,-1,-1,-1},
    {0,5,6,7,8,10,-1,-1,-1}, {17,19,20,22,23,-1,-1,-1,-1} },
  { {10,11,12,20,21,22,-1,-1,-1}, {1,2,3,4,5,6,10,21,20},
    {3,4,5,6,7,8,9,10,11},        {17,18,19,20,22,23,24,-1,-1} },
  { {0,5,9,13,19,22,-1,-1,-1}, {1,3,7,8,11,16,20,-1,-1},
    {4,6,11,12,18,24,25,-1,-1}, {5,6,10,14,19,23,-1,-1,-1} },
};
__constant__ int c_mask_len[3][4] = {{6,6,6,5},{6,9,9,7},{6,7,7,6}};

// ---------------- mma + cp.async helpers -------------------------------------
__device__ __forceinline__ void mma_f16(float* d, const unsigned* a,
                                        const unsigned* b) {
  asm volatile(
    "mma.sync.aligned.m16n8k16.row.col.f32.f16.f16.f32 "
    "{%0,%1,%2,%3}, {%4,%5,%6,%7}, {%8,%9}, {%0,%1,%2,%3};"
    : "+f"(d[0]), "+f"(d[1]), "+f"(d[2]), "+f"(d[3])
    : "r"(a[0]), "r"(a[1]), "r"(a[2]), "r"(a[3]), "r"(b[0]), "r"(b[1]));
}
__device__ __forceinline__ void cpa16(void* dst, const void* src) {
  unsigned d = (unsigned)__cvta_generic_to_shared(dst);
  asm volatile("cp.async.ca.shared.global [%0], [%1], 16;" :: "r"(d), "l"(src));
}
__device__ __forceinline__ void cpa16z(void* dst, const void* src, int sz) {
  unsigned d = (unsigned)__cvta_generic_to_shared(dst);
  asm volatile("cp.async.ca.shared.global [%0], [%1], 16, %2;"
               :: "r"(d), "l"(src), "r"(sz));
}
#define CPA_COMMIT() asm volatile("cp.async.commit_group;" ::: "memory")
#define CPA_WAIT1()  asm volatile("cp.async.wait_group 1;" ::: "memory")
#define CPA_WAIT0()  asm volatile("cp.async.wait_group 0;" ::: "memory")

// =============================================================================
// K0: one-shot fp16 conversions
// =============================================================================
__global__ __launch_bounds__(256) void k0_cvt_x(const float* __restrict__ x) {
  int i = blockIdx.x * 256 + threadIdx.x;
  int stride = gridDim.x * 256;
  for (; i < NPTS * PCH; i += stride) g_xh[i] = __float2half(x[i]);
}
__global__ __launch_bounds__(256) void k0_cvt_w1(const float* __restrict__ w) {
  int k = blockIdx.x;
  const float* src = w + k * PCH * PCH;     // [c][n]
  __half* dst = g_wh1 + k * PCH * PCH;      // [n][c]
  for (int i = threadIdx.x; i < PCH * PCH; i += 256) {
    int n = i / PCH, c = i % PCH;
    dst[i] = __float2half(src[c * PCH + n]);
  }
}
__global__ __launch_bounds__(256) void k0_cvt_qw(const float* __restrict__ qw) {
  int t = blockIdx.x;
  const float* src = qw + t * (PCH * 8);     // [c][n=8]
  __half* dst = g_qwh + t * (8 * PCH);       // [n][c]
  for (int i = threadIdx.x; i < 8 * PCH; i += 256) {
    int n = i / PCH, c = i % PCH;
    dst[i] = __float2half(src[c * 8 + n]);
  }
}
__global__ __launch_bounds__(256) void k0_cvt_w2(const float* __restrict__ w2) {
  int i = blockIdx.x * 256 + threadIdx.x;    // [c=96][j=192] -> [j][c]
  if (i < PCH * DIMC) {
    int j = i / PCH, c = i % PCH;
    g_w2h[i] = __float2half(w2[c * DIMC + j]);
  }
}
__global__ __launch_bounds__(256) void k0_cvt_ow(const float* __restrict__ ow) {
  int i = blockIdx.x * 256 + threadIdx.x;    // [c=192][j=96] -> [j][c]
  if (i < PCH * DIMC) {
    int j = i / DIMC, c = i % DIMC;
    g_owh[i] = __float2half(ow[c * PCH + j]);
  }
}

// =============================================================================
// K1 (fp16 mma, 2-stage): v1h = fp16(relu(BN( sum_k gather @ W[k] )))
// =============================================================================
#define K1_APAD 104
#define K1_AS (128 * K1_APAD)
#define K1_BS (96 * K1_APAD)
#define K1_STG (K1_AS + K1_BS)
#define K1_SMEM (2 * K1_STG * 2)              // 93184 bytes

__device__ __forceinline__ void k1_issue(
    __half* stg, const int* __restrict__ neis, int k, int n0, int tid)
{
  const int arow = tid >> 1, ahalf = tid & 1;
  int n = n0 + arow;
  int nr = (n < NPTS) ? __ldg(&neis[(KTAP + k) * NPTS + n]) : NPTS;
  int sz = (nr < NPTS) ? 16 : 0;
  const __half* srcA = g_xh + (size_t)(nr < NPTS ? nr : 0) * PCH + ahalf * 48;
  __half* dstA = stg + arow * K1_APAD + ahalf * 48;
  #pragma unroll
  for (int i = 0; i < 6; ++i) cpa16z(dstA + i * 8, srcA + i * 8, sz);
  const __half* srcB = g_wh1 + k * PCH * PCH;
  __half* Bs = stg + K1_AS;
  #pragma unroll
  for (int j = 0; j < 5; ++j) {
    int idx = tid + j * 256;
    if (idx < 1152) {
      int row = idx / 12, q = idx % 12;
      cpa16(Bs + row * K1_APAD + q * 8, srcB + row * PCH + q * 8);
    }
  }
}

__global__ __launch_bounds__(256) void k1_mma(
    const int* __restrict__ neis, const float* __restrict__ bng,
    const float* __restrict__ bnb)
{
  extern __shared__ char smem8[];
  __half* sm = (__half*)smem8;
  const int tid  = threadIdx.x;
  const int lane = tid & 31;
  const int wid  = tid >> 5;
  const int wm   = wid & 3;
  const int wn   = wid >> 2;
  const int n0   = blockIdx.x * 128;

  float d[2][6][4] = {};

  k1_issue(sm, neis, 0, n0, tid);
  CPA_COMMIT();

  for (int k = 0; k < KTAP; ++k) {
    if (k + 1 < KTAP) {
      k1_issue(sm + ((k + 1) & 1) * K1_STG, neis, k + 1, n0, tid);
      CPA_COMMIT();
      CPA_WAIT1();
    } else {
      CPA_WAIT0();
    }
    __syncthreads();
    const __half* As = sm + (k & 1) * K1_STG;
    const __half* Bs = As + K1_AS;
    #pragma unroll
    for (int ks = 0; ks < 6; ++ks) {
      unsigned a[2][4];
      {
        int c0 = ks * 16 + (lane & 3) * 2;
        #pragma unroll
        for (int mi = 0; mi < 2; ++mi) {
          int r = wm * 32 + mi * 16 + (lane >> 2);
          a[mi][0] = *(const unsigned*)&As[r * K1_APAD + c0];
          a[mi][1] = *(const unsigned*)&As[(r + 8) * K1_APAD + c0];
          a[mi][2] = *(const unsigned*)&As[r * K1_APAD + c0 + 8];
          a[mi][3] = *(const unsigned*)&As[(r + 8) * K1_APAD + c0 + 8];
        }
      }
      unsigned bf[6][2];
      {
        int kk = ks * 16 + (lane & 3) * 2;
        #pragma unroll
        for (int ni = 0; ni < 6; ++ni) {
          int n = wn * 48 + ni * 8 + (lane >> 2);
          bf[ni][0] = *(const unsigned*)&Bs[n * K1_APAD + kk];
          bf[ni][1] = *(const unsigned*)&Bs[n * K1_APAD + kk + 8];
        }
      }
      #pragma unroll
      for (int mi = 0; mi < 2; ++mi)
        #pragma unroll
        for (int ni = 0; ni < 6; ++ni)
          mma_f16(d[mi][ni], a[mi], bf[ni]);
    }
    __syncthreads();
  }

  #pragma unroll
  for (int mi = 0; mi < 2; ++mi) {
    int r0 = n0 + wm * 32 + mi * 16 + (lane >> 2);
    #pragma unroll
    for (int ni = 0; ni < 6; ++ni) {
      int c = wn * 48 + ni * 8 + (lane & 3) * 2;
      float g0 = __ldg(&bng[c]),     b0 = __ldg(&bnb[c]);
      float g1 = __ldg(&bng[c + 1]), b1 = __ldg(&bnb[c + 1]);
      if (r0 < NPTS) {
        float v0 = fmaxf(fmaf(d[mi][ni][0], g0, b0), 0.f);
        float v1 = fmaxf(fmaf(d[mi][ni][1], g1, b1), 0.f);
        *(__half2*)&g_v1h[(size_t)r0 * PCH + c] = __floats2half2_rn(v0, v1);
      }
      if (r0 + 8 < NPTS) {
        float v0 = fmaxf(fmaf(d[mi][ni][2], g0, b0), 0.f);
        float v1 = fmaxf(fmaf(d[mi][ni][3], g1, b1), 0.f);
        *(__half2*)&g_v1h[(size_t)(r0 + 8) * PCH + c] = __floats2half2_rn(v0, v1);
      }
    }
  }
}

// =============================================================================
// K2 (fp16 mma): v2h = fp16(relu(BN( v1h @ w_v2 )))  M=100k N=192(grid.y=2) K=96
// =============================================================================
#define K2_SMEM ((128 + 96) * K1_APAD * 2)    // 46592 bytes

__global__ __launch_bounds__(256) void k2_mma(
    const float* __restrict__ bng, const float* __restrict__ bnb)
{
  extern __shared__ char smem8[];
  __half* As = (__half*)smem8;                // [128][104]
  __half* Bs = As + 128 * K1_APAD;            // [96][104]
  const int tid  = threadIdx.x;
  const int lane = tid & 31;
  const int wid  = tid >> 5;
  const int wm   = wid & 3;
  const int wn   = wid >> 2;
  const int n0   = blockIdx.x * 128;
  const int j0   = blockIdx.y * 96;

  #pragma unroll
  for (int j = 0; j < 6; ++j) {
    int idx = tid + j * 256;                  // 1536 chunks A
    int row = idx / 12, q = idx % 12;
    int n = n0 + row;
    cpa16z(As + row * K1_APAD + q * 8,
           g_v1h + (size_t)(n < NPTS ? n : 0) * PCH + q * 8,
           (n < NPTS) ? 16 : 0);
  }
  #pragma unroll
  for (int j = 0; j < 5; ++j) {
    int idx = tid + j * 256;                  // 1152 chunks B
    if (idx < 1152) {
      int row = idx / 12, q = idx % 12;
      cpa16(Bs + row * K1_APAD + q * 8, g_w2h + (j0 + row) * PCH + q * 8);
    }
  }
  CPA_COMMIT(); CPA_WAIT0();
  __syncthreads();

  float d[2][6][4] = {};
  #pragma unroll
  for (int ks = 0; ks < 6; ++ks) {
    unsigned a[2][4];
    {
      int c0 = ks * 16 + (lane & 3) * 2;
      #pragma unroll
      for (int mi = 0; mi < 2; ++mi) {
        int r = wm * 32 + mi * 16 + (lane >> 2);
        a[mi][0] = *(const unsigned*)&As[r * K1_APAD + c0];
        a[mi][1] = *(const unsigned*)&As[(r + 8) * K1_APAD + c0];
        a[mi][2] = *(const unsigned*)&As[r * K1_APAD + c0 + 8];
        a[mi][3] = *(const unsigned*)&As[(r + 8) * K1_APAD + c0 + 8];
      }
    }
    unsigned bf[6][2];
    {
      int kk = ks * 16 + (lane & 3) * 2;
      #pragma unroll
      for (int ni = 0; ni < 6; ++ni) {
        int n = wn * 48 + ni * 8 + (lane >> 2);
        bf[ni][0] = *(const unsigned*)&Bs[n * K1_APAD + kk];
        bf[ni][1] = *(const unsigned*)&Bs[n * K1_APAD + kk + 8];
      }
    }
    #pragma unroll
    for (int mi = 0; mi < 2; ++mi)
      #pragma unroll
      for (int ni = 0; ni < 6; ++ni)
        mma_f16(d[mi][ni], a[mi], bf[ni]);
  }

  #pragma unroll
  for (int mi = 0; mi < 2; ++mi) {
    int r0 = n0 + wm * 32 + mi * 16 + (lane >> 2);
    #pragma unroll
    for (int ni = 0; ni < 6; ++ni) {
      int j = j0 + wn * 48 + ni * 8 + (lane & 3) * 2;
      float g0 = __ldg(&bng[j]),     b0 = __ldg(&bnb[j]);
      float g1 = __ldg(&bng[j + 1]), b1 = __ldg(&bnb[j + 1]);
      if (r0 < NPTS) {
        float v0 = fmaxf(fmaf(d[mi][ni][0], g0, b0), 0.f);
        float v1 = fmaxf(fmaf(d[mi][ni][1], g1, b1), 0.f);
        *(__half2*)&g_v2h[(size_t)r0 * DIMC + j] = __floats2half2_rn(v0, v1);
      }
      if (r0 + 8 < NPTS) {
        float v0 = fmaxf(fmaf(d[mi][ni][2], g0, b0), 0.f);
        float v1 = fmaxf(fmaf(d[mi][ni][3], g1, b1), 0.f);
        *(__half2*)&g_v2h[(size_t)(r0 + 8) * DIMC + j] = __floats2half2_rn(v0, v1);
      }
    }
  }
}

// =============================================================================
// K3 (fp16 mma + cp.async 2-stage): query convs -> choice weights
// =============================================================================
#define K3_AS (128 * K1_APAD)
#define K3_BS (8 * K1_APAD)
#define K3_STG (K3_AS + K3_BS)
#define K3_SMEM (2 * K3_STG * 2)

__device__ __forceinline__ void k3_issue(
    __half* stg, const int* __restrict__ neis, int t, int n0, int tid)
{
  const int arow = tid >> 1, ahalf = tid & 1;
  int n = n0 + arow;
  int nr = (n < NPTS) ? __ldg(&neis[t * NPTS + n]) : NPTS;
  int sz = (nr < NPTS) ? 16 : 0;
  const __half* srcA = g_xh + (size_t)(nr < NPTS ? nr : 0) * PCH + ahalf * 48;
  __half* dstA = stg + arow * K1_APAD + ahalf * 48;
  #pragma unroll
  for (int i = 0; i < 6; ++i) cpa16z(dstA + i * 8, srcA + i * 8, sz);
  if (tid < 96) {
    int row = tid / 12, q = tid % 12;
    cpa16(stg + K3_AS + row * K1_APAD + q * 8,
          g_qwh + t * (8 * PCH) + row * PCH + q * 8);
  }
}

__global__ __launch_bounds__(256) void k3_choice(
    const int* __restrict__ neis)
{
  extern __shared__ char smem8[];
  __half* sm = (__half*)smem8;
  const int tid  = threadIdx.x;
  const int lane = tid & 31;
  const int wid  = tid >> 5;
  const int n0   = blockIdx.x * 128;

  float acc[3][4] = {};

  k3_issue(sm, neis, 0, n0, tid);
  CPA_COMMIT();

  for (int t = 0; t < 3 * KTAP; ++t) {
    if (t + 1 < 3 * KTAP) {
      k3_issue(sm + ((t + 1) & 1) * K3_STG, neis, t + 1, n0, tid);
      CPA_COMMIT();
      CPA_WAIT1();
    } else {
      CPA_WAIT0();
    }
    __syncthreads();
    const __half* As = sm + (t & 1) * K3_STG;
    const __half* Bs = As + K3_AS;
    const int dd = t / KTAP;
    const int r  = wid * 16 + (lane >> 2);
    #pragma unroll
    for (int ks = 0; ks < 6; ++ks) {
      int c0 = ks * 16 + (lane & 3) * 2;
      unsigned a[4];
      a[0] = *(const unsigned*)&As[r * K1_APAD + c0];
      a[1] = *(const unsigned*)&As[(r + 8) * K1_APAD + c0];
      a[2] = *(const unsigned*)&As[r * K1_APAD + c0 + 8];
      a[3] = *(const unsigned*)&As[(r + 8) * K1_APAD + c0 + 8];
      unsigned bf[2];
      int n = lane >> 2;
      bf[0] = *(const unsigned*)&Bs[n * K1_APAD + c0];
      bf[1] = *(const unsigned*)&Bs[n * K1_APAD + c0 + 8];
      mma_f16(acc[dd], a, bf);
    }
    __syncthreads();
  }

  float* qsm = (float*)smem8;   // [128][25]
  {
    int r = wid * 16 + (lane >> 2);
    int c2 = (lane & 3) * 2;
    #pragma unroll
    for (int d = 0; d < 3; ++d) {
      qsm[r * 25 + d * 8 + c2]           = acc[d][0];
      qsm[r * 25 + d * 8 + c2 + 1]       = acc[d][1];
      qsm[(r + 8) * 25 + d * 8 + c2]     = acc[d][2];
      qsm[(r + 8) * 25 + d * 8 + c2 + 1] = acc[d][3];
    }
  }
  __syncthreads();

  if (tid < 128) {
    int n = n0 + tid;
    if (n < NPTS) {
      float t1[3][8];
      #pragma unroll
      for (int d = 0; d < 3; ++d) {
        unsigned pb = 0;
        #pragma unroll 1
        for (int k = 0; k < KTAP; ++k)
          pb |= (unsigned)(neis[(d*KTAP + k)*NPTS + n] < NPTS) << k;
        float v[8];
        #pragma unroll
        for (int mi = 0; mi < 4; ++mi) {
          unsigned ex = 0;
          #pragma unroll
          for (int tt = 0; tt < 9; ++tt) {
            int it = c_mask_items[d][mi][tt];
            if (it >= 0) ex |= (1u << it);
          }
          float keepinv = 1.f / (float)(27 - c_mask_len[d][mi]);
          float spv = (float)__popc(pb & ~ex & 0x7FFFFFFu) * keepinv;
          v[mi] = (spv + 1e-3f) * 5.f;
        }
        #pragma unroll
        for (int mi = 4; mi < 8; ++mi) v[mi] = 5e-3f;
        float mx = v[0];
        #pragma unroll
        for (int m = 1; m < 8; ++m) mx = fmaxf(mx, v[m]);
        float s = 0.f;
        #pragma unroll
        for (int m = 0; m < 8; ++m) { v[m] = __expf(v[m] - mx); s += v[m]; }
        float inv = 1.f / s;
        #pragma unroll
        for (int m = 0; m < 8; ++m) t1[d][m] = v[m] * inv;
      }
      #pragma unroll
      for (int m = 0; m < 8; ++m) {
        float a0 = (t1[0][m] + 1e-3f) * 5.f;
        float a1 = (t1[1][m] + 1e-3f) * 5.f;
        float a2 = (t1[2][m] + 1e-3f) * 5.f;
        float mx = fmaxf(a0, fmaxf(a1, a2));
        float e0 = __expf(a0 - mx), e1 = __expf(a1 - mx), e2 = __expf(a2 - mx);
        float inv = 1.f / (e0 + e1 + e2);
        t1[0][m] = e0 * inv; t1[1][m] = e1 * inv; t1[2][m] = e2 * inv;
      }
      #pragma unroll
      for (int d = 0; d < 3; ++d) {
        float sv[8];
        float mx = -1e30f;
        #pragma unroll
        for (int m = 0; m < 8; ++m) {
          sv[m] = qsm[tid*25 + d*8 + m] * 0.70710678118654752f;
          mx = fmaxf(mx, sv[m]);
        }
        float s = 0.f;
        #pragma unroll
        for (int m = 0; m < 8; ++m) { sv[m] = __expf(sv[m] - mx); s += sv[m]; }
        float inv = 1.f / s;
        #pragma unroll
        for (int m = 0; m < 8; ++m)
          g_choice[n*24 + d*8 + m] = sv[m] * inv * t1[d][m];
      }
    }
  }
}

// =============================================================================
// K4: aggh[n,c] = fp16( sum_d choice * sum_k cb[d,k,c] * v2h[neis[d,k,n],c] )
// warp-per-point; 27 indices preloaded, gather loop unrolled for MLP
// =============================================================================
__global__ __launch_bounds__(256) void k4_agg(
    const int* __restrict__ neis, const float* __restrict__ cb)
{
  extern __shared__ float ks[];   // 3*27*192 floats
  for (int i = threadIdx.x; i < 3888; i += 256)
    ((float4*)ks)[i] = ((const float4*)cb)[i];
  __syncthreads();

  const int lane = threadIdx.x & 31;
  const int w    = threadIdx.x >> 5;
  const int n0   = blockIdx.x * 128 + w * 16;

  for (int pi = 0; pi < 16; ++pi) {
    int n = n0 + pi;
    if (n >= NPTS) break;
    float agg[6] = {0.f,0.f,0.f,0.f,0.f,0.f};
    #pragma unroll
    for (int d = 0; d < 3; ++d) {
      const int* nd = neis + d*KTAP*NPTS + n;
      int rr[KTAP];
      #pragma unroll
      for (int k = 0; k < KTAP; ++k) rr[k] = __ldg(&nd[k*NPTS]);
      float pd[6] = {0.f,0.f,0.f,0.f,0.f,0.f};
      #pragma unroll 9
      for (int k = 0; k < KTAP; ++k) {
        int r = rr[k];
        if (r < NPTS) {
          const __half2* vr = (const __half2*)(g_v2h + (size_t)r * DIMC);
          const float* kk = ks + (d*KTAP + k)*DIMC;
          #pragma unroll
          for (int i = 0; i < 3; ++i) {
            float2 f = __half22float2(vr[lane + 32*i]);
            int c = lane*2 + 64*i;
            pd[2*i]   = fmaf(kk[c],   f.x, pd[2*i]);
            pd[2*i+1] = fmaf(kk[c+1], f.y, pd[2*i+1]);
          }
        }
      }
      #pragma unroll
      for (int i = 0; i < 3; ++i) {
        int c = lane*2 + 64*i;
        float ch = g_choice[n*24 + d*8 + (c/24)];
        agg[2*i]   += pd[2*i]   * ch;
        agg[2*i+1] += pd[2*i+1] * ch;
      }
    }
    #pragma unroll
    for (int i = 0; i < 3; ++i) {
      int c = lane*2 + 64*i;
      *(__half2*)&g_aggh[(size_t)n*DIMC + c] =
          __floats2half2_rn(agg[2*i], agg[2*i+1]);
    }
  }
}

// =============================================================================
// K5 (fp16 mma): out = relu(BN( aggh @ out_w )) + x   M=100k N=96 K=192
// =============================================================================
#define K5_APAD 200
#define K5_SMEM ((128 + 96) * K5_APAD * 2)    // 89600 bytes

__global__ __launch_bounds__(256) void k5_mma(
    const float* __restrict__ x, const float* __restrict__ bng,
    const float* __restrict__ bnb, float* __restrict__ out)
{
  extern __shared__ char smem8[];
  __half* As = (__half*)smem8;                // [128][200]
  __half* Bs = As + 128 * K5_APAD;            // [96][200]
  const int tid  = threadIdx.x;
  const int lane = tid & 31;
  const int wid  = tid >> 5;
  const int wm   = wid & 3;
  const int wn   = wid >> 2;
  const int n0   = blockIdx.x * 128;

  #pragma unroll
  for (int j = 0; j < 12; ++j) {
    int idx = tid + j * 256;                  // 3072 chunks A (128 x 24)
    int row = idx / 24, q = idx % 24;
    int n = n0 + row;
    cpa16z(As + row * K5_APAD + q * 8,
           g_aggh + (size_t)(n < NPTS ? n : 0) * DIMC + q * 8,
           (n < NPTS) ? 16 : 0);
  }
  #pragma unroll
  for (int j = 0; j < 9; ++j) {
    int idx = tid + j * 256;                  // 2304 chunks B (96 x 24)
    int row = idx / 24, q = idx % 24;
    cpa16(Bs + row * K5_APAD + q * 8, g_owh + row * DIMC + q * 8);
  }
  CPA_COMMIT(); CPA_WAIT0();
  __syncthreads();

  float d[2][6][4] = {};
  #pragma unroll
  for (int ks = 0; ks < 12; ++ks) {
    unsigned a[2][4];
    {
      int c0 = ks * 16 + (lane & 3) * 2;
      #pragma unroll
      for (int mi = 0; mi < 2; ++mi) {
        int r = wm * 32 + mi * 16 + (lane >> 2);
        a[mi][0] = *(const unsigned*)&As[r * K5_APAD + c0];
        a[mi][1] = *(const unsigned*)&As[(r + 8) * K5_APAD + c0];
        a[mi][2] = *(const unsigned*)&As[r * K5_APAD + c0 + 8];
        a[mi][3] = *(const unsigned*)&As[(r + 8) * K5_APAD + c0 + 8];
      }
    }
    unsigned bf[6][2];
    {
      int kk = ks * 16 + (lane & 3) * 2;
      #pragma unroll
      for (int ni = 0; ni < 6; ++ni) {
        int n = wn * 48 + ni * 8 + (lane >> 2);
        bf[ni][0] = *(const unsigned*)&Bs[n * K5_APAD + kk];
        bf[ni][1] = *(const unsigned*)&Bs[n * K5_APAD + kk + 8];
      }
    }
    #pragma unroll
    for (int mi = 0; mi < 2; ++mi)
      #pragma unroll
      for (int ni = 0; ni < 6; ++ni)
        mma_f16(d[mi][ni], a[mi], bf[ni]);
  }

  #pragma unroll
  for (int mi = 0; mi < 2; ++mi) {
    int r0 = n0 + wm * 32 + mi * 16 + (lane >> 2);
    #pragma unroll
    for (int ni = 0; ni < 6; ++ni) {
      int c = wn * 48 + ni * 8 + (lane & 3) * 2;
      float g0 = __ldg(&bng[c]),     b0 = __ldg(&bnb[c]);
      float g1 = __ldg(&bng[c + 1]), b1 = __ldg(&bnb[c + 1]);
      if (r0 < NPTS) {
        float2 v;
        v.x = fmaxf(fmaf(d[mi][ni][0], g0, b0), 0.f) + x[(size_t)r0 * PCH + c];
        v.y = fmaxf(fmaf(d[mi][ni][1], g1, b1), 0.f) + x[(size_t)r0 * PCH + c + 1];
        *(float2*)&out[(size_t)r0 * PCH + c] = v;
      }
      if (r0 + 8 < NPTS) {
        float2 v;
        v.x = fmaxf(fmaf(d[mi][ni][2], g0, b0), 0.f) + x[(size_t)(r0+8) * PCH + c];
        v.y = fmaxf(fmaf(d[mi][ni][3], g1, b1), 0.f) + x[(size_t)(r0+8) * PCH + c + 1];
        *(float2*)&out[(size_t)(r0 + 8) * PCH + c] = v;
      }
    }
  }
}

// =============================================================================
extern "C" void kernel_launch(void* const* d_in, const int* in_sizes, int n_in,
                              void* d_out, int out_size)
{
  const float* x    = (const float*)d_in[0];
  const int*   neis = (const int*)  d_in[1];
  const float* w_v1 = (const float*)d_in[2];
  const float* bn1g = (const float*)d_in[3];
  const float* bn1b = (const float*)d_in[4];
  const float* w_v2 = (const float*)d_in[5];
  const float* bn2g = (const float*)d_in[6];
  const float* bn2b = (const float*)d_in[7];
  const float* q_w  = (const float*)d_in[8];
  const float* cbk  = (const float*)d_in[9];
  const float* outw = (const float*)d_in[10];
  const float* obng = (const float*)d_in[11];
  const float* obnb = (const float*)d_in[12];
  float* out = (float*)d_out;

  const int SM4 = 15552 * 4;

  cudaFuncSetAttribute(k1_mma,   cudaFuncAttributeMaxDynamicSharedMemorySize, K1_SMEM);
  cudaFuncSetAttribute(k2_mma,   cudaFuncAttributeMaxDynamicSharedMemorySize, K2_SMEM);
  cudaFuncSetAttribute(k3_choice,cudaFuncAttributeMaxDynamicSharedMemorySize, K3_SMEM);
  cudaFuncSetAttribute(k4_agg,   cudaFuncAttributeMaxDynamicSharedMemorySize, SM4);
  cudaFuncSetAttribute(k5_mma,   cudaFuncAttributeMaxDynamicSharedMemorySize, K5_SMEM);

  k0_cvt_x  <<<512, 256>>>(x);
  k0_cvt_w1 <<<KTAP, 256>>>(w_v1);
  k0_cvt_qw <<<3 * KTAP, 256>>>(q_w);
  k0_cvt_w2 <<<(PCH * DIMC + 255) / 256, 256>>>(w_v2);
  k0_cvt_ow <<<(PCH * DIMC + 255) / 256, 256>>>(outw);

  k1_mma    <<<(NPTS + 127) / 128, 256, K1_SMEM>>>(neis, bn1g, bn1b);
  k2_mma    <<<dim3((NPTS + 127) / 128, 2), 256, K2_SMEM>>>(bn2g, bn2b);
  k3_choice <<<(NPTS + 127) / 128, 256, K3_SMEM>>>(neis);
  k4_agg    <<<(NPTS + 127) / 128, 256, SM4>>>(neis, cbk);
  k5_mma    <<<(NPTS + 127) / 128, 256, K5_SMEM>>>(x, obng, obnb, out);
}

// round 8
// speedup vs baseline: 3.2644x; 1.1257x over previous
#include <cuda_runtime.h>
#include <cuda_fp16.h>

#define NPTS 100000
#define PCH  96
#define DIMC 192
#define KTAP 27

// ---------------- scratch (static device globals; no allocation) ------------
__device__ __half g_v1h[NPTS * PCH];          // v1 fp16
__device__ __half g_v2h[NPTS * DIMC];         // v2 fp16
__device__ float  g_choice[NPTS * 24];
__device__ __half g_aggh[NPTS * DIMC];        // agg fp16
__device__ __half g_xh[NPTS * PCH];           // x fp16
__device__ __half g_wh1[KTAP * PCH * PCH];    // w_v1 fp16 [k][n][c]
__device__ __half g_qwh[3 * KTAP * 8 * PCH];  // q_w fp16  [t][n=8][c=96]
__device__ __half g_w2h[DIMC * PCH];          // w_v2 fp16 [j=192][c=96]
__device__ __half g_owh[PCH * DIMC];          // out_w fp16 [j=96][c=192]

// ---------------- sparse-pattern masks --------------------------------------
__constant__ int c_mask_items[3][4][9] = {
  { {0,1,3,6,7,13,-1,-1,-1}, {1,2,9,14,15,17,-1,-1,-1},
    {0,5,6,7,8,10,-1,-1,-1}, {17,19,20,22,23,-1,-1,-1,-1} },
  { {10,11,12,20,21,22,-1,-1,-1}, {1,2,3,4,5,6,10,21,20},
    {3,4,5,6,7,8,9,10,11},        {17,18,19,20,22,23,24,-1,-1} },
  { {0,5,9,13,19,22,-1,-1,-1}, {1,3,7,8,11,16,20,-1,-1},
    {4,6,11,12,18,24,25,-1,-1}, {5,6,10,14,19,23,-1,-1,-1} },
};
__constant__ int c_mask_len[3][4] = {{6,6,6,5},{6,9,9,7},{6,7,7,6}};

// ---------------- mma + cp.async helpers -------------------------------------
__device__ __forceinline__ void mma_f16(float* d, const unsigned* a,
                                        const unsigned* b) {
  asm volatile(
    "mma.sync.aligned.m16n8k16.row.col.f32.f16.f16.f32 "
    "{%0,%1,%2,%3}, {%4,%5,%6,%7}, {%8,%9}, {%0,%1,%2,%3};"
    : "+f"(d[0]), "+f"(d[1]), "+f"(d[2]), "+f"(d[3])
    : "r"(a[0]), "r"(a[1]), "r"(a[2]), "r"(a[3]), "r"(b[0]), "r"(b[1]));
}
__device__ __forceinline__ void cpa16(void* dst, const void* src) {
  unsigned d = (unsigned)__cvta_generic_to_shared(dst);
  asm volatile("cp.async.ca.shared.global [%0], [%1], 16;" :: "r"(d), "l"(src));
}
__device__ __forceinline__ void cpa16z(void* dst, const void* src, int sz) {
  unsigned d = (unsigned)__cvta_generic_to_shared(dst);
  asm volatile("cp.async.ca.shared.global [%0], [%1], 16, %2;"
               :: "r"(d), "l"(src), "r"(sz));
}
#define CPA_COMMIT() asm volatile("cp.async.commit_group;" ::: "memory")
#define CPA_WAIT1()  asm volatile("cp.async.wait_group 1;" ::: "memory")
#define CPA_WAIT3()  asm volatile("cp.async.wait_group 3;" ::: "memory")
#define CPA_WAIT0()  asm volatile("cp.async.wait_group 0;" ::: "memory")

// =============================================================================
// K0: one-shot fp16 conversions
// =============================================================================
__global__ __launch_bounds__(256) void k0_cvt_x(const float* __restrict__ x) {
  int i = blockIdx.x * 256 + threadIdx.x;
  int stride = gridDim.x * 256;
  for (; i < NPTS * PCH; i += stride) g_xh[i] = __float2half(x[i]);
}
__global__ __launch_bounds__(256) void k0_cvt_w1(const float* __restrict__ w) {
  int k = blockIdx.x;
  const float* src = w + k * PCH * PCH;     // [c][n]
  __half* dst = g_wh1 + k * PCH * PCH;      // [n][c]
  for (int i = threadIdx.x; i < PCH * PCH; i += 256) {
    int n = i / PCH, c = i % PCH;
    dst[i] = __float2half(src[c * PCH + n]);
  }
}
__global__ __launch_bounds__(256) void k0_cvt_qw(const float* __restrict__ qw) {
  int t = blockIdx.x;
  const float* src = qw + t * (PCH * 8);     // [c][n=8]
  __half* dst = g_qwh + t * (8 * PCH);       // [n][c]
  for (int i = threadIdx.x; i < 8 * PCH; i += 256) {
    int n = i / PCH, c = i % PCH;
    dst[i] = __float2half(src[c * 8 + n]);
  }
}
__global__ __launch_bounds__(256) void k0_cvt_w2(const float* __restrict__ w2) {
  int i = blockIdx.x * 256 + threadIdx.x;    // [c=96][j=192] -> [j][c]
  if (i < PCH * DIMC) {
    int j = i / PCH, c = i % PCH;
    g_w2h[i] = __float2half(w2[c * DIMC + j]);
  }
}
__global__ __launch_bounds__(256) void k0_cvt_ow(const float* __restrict__ ow) {
  int i = blockIdx.x * 256 + threadIdx.x;    // [c=192][j=96] -> [j][c]
  if (i < PCH * DIMC) {
    int j = i / DIMC, c = i % DIMC;
    g_owh[i] = __float2half(ow[c * PCH + j]);
  }
}

// =============================================================================
// K1 (fp16 mma, 2-stage): v1h = fp16(relu(BN( sum_k gather @ W[k] )))
// =============================================================================
#define K1_APAD 104
#define K1_AS (128 * K1_APAD)
#define K1_BS (96 * K1_APAD)
#define K1_STG (K1_AS + K1_BS)
#define K1_SMEM (2 * K1_STG * 2)              // 93184 bytes

__device__ __forceinline__ void k1_issue(
    __half* stg, const int* __restrict__ neis, int k, int n0, int tid)
{
  const int arow = tid >> 1, ahalf = tid & 1;
  int n = n0 + arow;
  int nr = (n < NPTS) ? __ldg(&neis[(KTAP + k) * NPTS + n]) : NPTS;
  int sz = (nr < NPTS) ? 16 : 0;
  const __half* srcA = g_xh + (size_t)(nr < NPTS ? nr : 0) * PCH + ahalf * 48;
  __half* dstA = stg + arow * K1_APAD + ahalf * 48;
  #pragma unroll
  for (int i = 0; i < 6; ++i) cpa16z(dstA + i * 8, srcA + i * 8, sz);
  const __half* srcB = g_wh1 + k * PCH * PCH;
  __half* Bs = stg + K1_AS;
  #pragma unroll
  for (int j = 0; j < 5; ++j) {
    int idx = tid + j * 256;
    if (idx < 1152) {
      int row = idx / 12, q = idx % 12;
      cpa16(Bs + row * K1_APAD + q * 8, srcB + row * PCH + q * 8);
    }
  }
}

__global__ __launch_bounds__(256) void k1_mma(
    const int* __restrict__ neis, const float* __restrict__ bng,
    const float* __restrict__ bnb)
{
  extern __shared__ char smem8[];
  __half* sm = (__half*)smem8;
  const int tid  = threadIdx.x;
  const int lane = tid & 31;
  const int wid  = tid >> 5;
  const int wm   = wid & 3;
  const int wn   = wid >> 2;
  const int n0   = blockIdx.x * 128;

  float d[2][6][4] = {};

  k1_issue(sm, neis, 0, n0, tid);
  CPA_COMMIT();

  for (int k = 0; k < KTAP; ++k) {
    if (k + 1 < KTAP) {
      k1_issue(sm + ((k + 1) & 1) * K1_STG, neis, k + 1, n0, tid);
      CPA_COMMIT();
      CPA_WAIT1();
    } else {
      CPA_WAIT0();
    }
    __syncthreads();
    const __half* As = sm + (k & 1) * K1_STG;
    const __half* Bs = As + K1_AS;
    #pragma unroll
    for (int ks = 0; ks < 6; ++ks) {
      unsigned a[2][4];
      {
        int c0 = ks * 16 + (lane & 3) * 2;
        #pragma unroll
        for (int mi = 0; mi < 2; ++mi) {
          int r = wm * 32 + mi * 16 + (lane >> 2);
          a[mi][0] = *(const unsigned*)&As[r * K1_APAD + c0];
          a[mi][1] = *(const unsigned*)&As[(r + 8) * K1_APAD + c0];
          a[mi][2] = *(const unsigned*)&As[r * K1_APAD + c0 + 8];
          a[mi][3] = *(const unsigned*)&As[(r + 8) * K1_APAD + c0 + 8];
        }
      }
      unsigned bf[6][2];
      {
        int kk = ks * 16 + (lane & 3) * 2;
        #pragma unroll
        for (int ni = 0; ni < 6; ++ni) {
          int n = wn * 48 + ni * 8 + (lane >> 2);
          bf[ni][0] = *(const unsigned*)&Bs[n * K1_APAD + kk];
          bf[ni][1] = *(const unsigned*)&Bs[n * K1_APAD + kk + 8];
        }
      }
      #pragma unroll
      for (int mi = 0; mi < 2; ++mi)
        #pragma unroll
        for (int ni = 0; ni < 6; ++ni)
          mma_f16(d[mi][ni], a[mi], bf[ni]);
    }
    __syncthreads();
  }

  #pragma unroll
  for (int mi = 0; mi < 2; ++mi) {
    int r0 = n0 + wm * 32 + mi * 16 + (lane >> 2);
    #pragma unroll
    for (int ni = 0; ni < 6; ++ni) {
      int c = wn * 48 + ni * 8 + (lane & 3) * 2;
      float g0 = __ldg(&bng[c]),     b0 = __ldg(&bnb[c]);
      float g1 = __ldg(&bng[c + 1]), b1 = __ldg(&bnb[c + 1]);
      if (r0 < NPTS) {
        float v0 = fmaxf(fmaf(d[mi][ni][0], g0, b0), 0.f);
        float v1 = fmaxf(fmaf(d[mi][ni][1], g1, b1), 0.f);
        *(__half2*)&g_v1h[(size_t)r0 * PCH + c] = __floats2half2_rn(v0, v1);
      }
      if (r0 + 8 < NPTS) {
        float v0 = fmaxf(fmaf(d[mi][ni][2], g0, b0), 0.f);
        float v1 = fmaxf(fmaf(d[mi][ni][3], g1, b1), 0.f);
        *(__half2*)&g_v1h[(size_t)(r0 + 8) * PCH + c] = __floats2half2_rn(v0, v1);
      }
    }
  }
}

// =============================================================================
// K2 (fp16 mma): v2h = fp16(relu(BN( v1h @ w_v2 )))
// =============================================================================
#define K2_SMEM ((128 + 96) * K1_APAD * 2)

__global__ __launch_bounds__(256) void k2_mma(
    const float* __restrict__ bng, const float* __restrict__ bnb)
{
  extern __shared__ char smem8[];
  __half* As = (__half*)smem8;
  __half* Bs = As + 128 * K1_APAD;
  const int tid  = threadIdx.x;
  const int lane = tid & 31;
  const int wid  = tid >> 5;
  const int wm   = wid & 3;
  const int wn   = wid >> 2;
  const int n0   = blockIdx.x * 128;
  const int j0   = blockIdx.y * 96;

  #pragma unroll
  for (int j = 0; j < 6; ++j) {
    int idx = tid + j * 256;
    int row = idx / 12, q = idx % 12;
    int n = n0 + row;
    cpa16z(As + row * K1_APAD + q * 8,
           g_v1h + (size_t)(n < NPTS ? n : 0) * PCH + q * 8,
           (n < NPTS) ? 16 : 0);
  }
  #pragma unroll
  for (int j = 0; j < 5; ++j) {
    int idx = tid + j * 256;
    if (idx < 1152) {
      int row = idx / 12, q = idx % 12;
      cpa16(Bs + row * K1_APAD + q * 8, g_w2h + (j0 + row) * PCH + q * 8);
    }
  }
  CPA_COMMIT(); CPA_WAIT0();
  __syncthreads();

  float d[2][6][4] = {};
  #pragma unroll
  for (int ks = 0; ks < 6; ++ks) {
    unsigned a[2][4];
    {
      int c0 = ks * 16 + (lane & 3) * 2;
      #pragma unroll
      for (int mi = 0; mi < 2; ++mi) {
        int r = wm * 32 + mi * 16 + (lane >> 2);
        a[mi][0] = *(const unsigned*)&As[r * K1_APAD + c0];
        a[mi][1] = *(const unsigned*)&As[(r + 8) * K1_APAD + c0];
        a[mi][2] = *(const unsigned*)&As[r * K1_APAD + c0 + 8];
        a[mi][3] = *(const unsigned*)&As[(r + 8) * K1_APAD + c0 + 8];
      }
    }
    unsigned bf[6][2];
    {
      int kk = ks * 16 + (lane & 3) * 2;
      #pragma unroll
      for (int ni = 0; ni < 6; ++ni) {
        int n = wn * 48 + ni * 8 + (lane >> 2);
        bf[ni][0] = *(const unsigned*)&Bs[n * K1_APAD + kk];
        bf[ni][1] = *(const unsigned*)&Bs[n * K1_APAD + kk + 8];
      }
    }
    #pragma unroll
    for (int mi = 0; mi < 2; ++mi)
      #pragma unroll
      for (int ni = 0; ni < 6; ++ni)
        mma_f16(d[mi][ni], a[mi], bf[ni]);
  }

  #pragma unroll
  for (int mi = 0; mi < 2; ++mi) {
    int r0 = n0 + wm * 32 + mi * 16 + (lane >> 2);
    #pragma unroll
    for (int ni = 0; ni < 6; ++ni) {
      int j = j0 + wn * 48 + ni * 8 + (lane & 3) * 2;
      float g0 = __ldg(&bng[j]),     b0 = __ldg(&bnb[j]);
      float g1 = __ldg(&bng[j + 1]), b1 = __ldg(&bnb[j + 1]);
      if (r0 < NPTS) {
        float v0 = fmaxf(fmaf(d[mi][ni][0], g0, b0), 0.f);
        float v1 = fmaxf(fmaf(d[mi][ni][1], g1, b1), 0.f);
        *(__half2*)&g_v2h[(size_t)r0 * DIMC + j] = __floats2half2_rn(v0, v1);
      }
      if (r0 + 8 < NPTS) {
        float v0 = fmaxf(fmaf(d[mi][ni][2], g0, b0), 0.f);
        float v1 = fmaxf(fmaf(d[mi][ni][3], g1, b1), 0.f);
        *(__half2*)&g_v2h[(size_t)(r0 + 8) * DIMC + j] = __floats2half2_rn(v0, v1);
      }
    }
  }
}

// =============================================================================
// K3 (fp16 mma + cp.async 4-stage): query convs -> choice weights
// =============================================================================
#define K3_AS (128 * K1_APAD)
#define K3_BS (8 * K1_APAD)
#define K3_STG (K3_AS + K3_BS)
#define K3_SMEM (4 * K3_STG * 2)              // 113152 bytes

__device__ __forceinline__ void k3_issue(
    __half* stg, const int* __restrict__ neis, int t, int n0, int tid)
{
  const int arow = tid >> 1, ahalf = tid & 1;
  int n = n0 + arow;
  int nr = (n < NPTS) ? __ldg(&neis[t * NPTS + n]) : NPTS;
  int sz = (nr < NPTS) ? 16 : 0;
  const __half* srcA = g_xh + (size_t)(nr < NPTS ? nr : 0) * PCH + ahalf * 48;
  __half* dstA = stg + arow * K1_APAD + ahalf * 48;
  #pragma unroll
  for (int i = 0; i < 6; ++i) cpa16z(dstA + i * 8, srcA + i * 8, sz);
  if (tid < 96) {
    int row = tid / 12, q = tid % 12;
    cpa16(stg + K3_AS + row * K1_APAD + q * 8,
          g_qwh + t * (8 * PCH) + row * PCH + q * 8);
  }
}

__global__ __launch_bounds__(256) void k3_choice(
    const int* __restrict__ neis)
{
  extern __shared__ char smem8[];
  __half* sm = (__half*)smem8;
  const int tid  = threadIdx.x;
  const int lane = tid & 31;
  const int wid  = tid >> 5;
  const int n0   = blockIdx.x * 128;

  float acc[3][4] = {};

  #pragma unroll
  for (int p = 0; p < 3; ++p) {
    k3_issue(sm + p * K3_STG, neis, p, n0, tid);
    CPA_COMMIT();
  }

  for (int t = 0; t < 3 * KTAP; ++t) {
    if (t + 3 < 3 * KTAP)
      k3_issue(sm + ((t + 3) & 3) * K3_STG, neis, t + 3, n0, tid);
    CPA_COMMIT();
    CPA_WAIT3();
    __syncthreads();
    const __half* As = sm + (t & 3) * K3_STG;
    const __half* Bs = As + K3_AS;
    const int dd = t / KTAP;
    const int r  = wid * 16 + (lane >> 2);
    #pragma unroll
    for (int ks = 0; ks < 6; ++ks) {
      int c0 = ks * 16 + (lane & 3) * 2;
      unsigned a[4];
      a[0] = *(const unsigned*)&As[r * K1_APAD + c0];
      a[1] = *(const unsigned*)&As[(r + 8) * K1_APAD + c0];
      a[2] = *(const unsigned*)&As[r * K1_APAD + c0 + 8];
      a[3] = *(const unsigned*)&As[(r + 8) * K1_APAD + c0 + 8];
      unsigned bf[2];
      int n = lane >> 2;
      bf[0] = *(const unsigned*)&Bs[n * K1_APAD + c0];
      bf[1] = *(const unsigned*)&Bs[n * K1_APAD + c0 + 8];
      mma_f16(acc[dd], a, bf);
    }
    __syncthreads();
  }

  float* qsm = (float*)smem8;   // [128][25]
  {
    int r = wid * 16 + (lane >> 2);
    int c2 = (lane & 3) * 2;
    #pragma unroll
    for (int d = 0; d < 3; ++d) {
      qsm[r * 25 + d * 8 + c2]           = acc[d][0];
      qsm[r * 25 + d * 8 + c2 + 1]       = acc[d][1];
      qsm[(r + 8) * 25 + d * 8 + c2]     = acc[d][2];
      qsm[(r + 8) * 25 + d * 8 + c2 + 1] = acc[d][3];
    }
  }
  __syncthreads();

  if (tid < 128) {
    int n = n0 + tid;
    if (n < NPTS) {
      float t1[3][8];
      #pragma unroll
      for (int d = 0; d < 3; ++d) {
        unsigned pb = 0;
        #pragma unroll 1
        for (int k = 0; k < KTAP; ++k)
          pb |= (unsigned)(neis[(d*KTAP + k)*NPTS + n] < NPTS) << k;
        float v[8];
        #pragma unroll
        for (int mi = 0; mi < 4; ++mi) {
          unsigned ex = 0;
          #pragma unroll
          for (int tt = 0; tt < 9; ++tt) {
            int it = c_mask_items[d][mi][tt];
            if (it >= 0) ex |= (1u << it);
          }
          float keepinv = 1.f / (float)(27 - c_mask_len[d][mi]);
          float spv = (float)__popc(pb & ~ex & 0x7FFFFFFu) * keepinv;
          v[mi] = (spv + 1e-3f) * 5.f;
        }
        #pragma unroll
        for (int mi = 4; mi < 8; ++mi) v[mi] = 5e-3f;
        float mx = v[0];
        #pragma unroll
        for (int m = 1; m < 8; ++m) mx = fmaxf(mx, v[m]);
        float s = 0.f;
        #pragma unroll
        for (int m = 0; m < 8; ++m) { v[m] = __expf(v[m] - mx); s += v[m]; }
        float inv = 1.f / s;
        #pragma unroll
        for (int m = 0; m < 8; ++m) t1[d][m] = v[m] * inv;
      }
      #pragma unroll
      for (int m = 0; m < 8; ++m) {
        float a0 = (t1[0][m] + 1e-3f) * 5.f;
        float a1 = (t1[1][m] + 1e-3f) * 5.f;
        float a2 = (t1[2][m] + 1e-3f) * 5.f;
        float mx = fmaxf(a0, fmaxf(a1, a2));
        float e0 = __expf(a0 - mx), e1 = __expf(a1 - mx), e2 = __expf(a2 - mx);
        float inv = 1.f / (e0 + e1 + e2);
        t1[0][m] = e0 * inv; t1[1][m] = e1 * inv; t1[2][m] = e2 * inv;
      }
      #pragma unroll
      for (int d = 0; d < 3; ++d) {
        float sv[8];
        float mx = -1e30f;
        #pragma unroll
        for (int m = 0; m < 8; ++m) {
          sv[m] = qsm[tid*25 + d*8 + m] * 0.70710678118654752f;
          mx = fmaxf(mx, sv[m]);
        }
        float s = 0.f;
        #pragma unroll
        for (int m = 0; m < 8; ++m) { sv[m] = __expf(sv[m] - mx); s += sv[m]; }
        float inv = 1.f / s;
        #pragma unroll
        for (int m = 0; m < 8; ++m)
          g_choice[n*24 + d*8 + m] = sv[m] * inv * t1[d][m];
      }
    }
  }
}

// =============================================================================
// K4: aggh = fp16(sum_d choice * sum_k cb*gather(v2h)); cb staged as fp16
// =============================================================================
#define K4_SMEM (15552 * 2)       // 15552 halfs = 31104 bytes (FIXED)

__global__ __launch_bounds__(256) void k4_agg(
    const int* __restrict__ neis, const float* __restrict__ cb)
{
  extern __shared__ char smem8[];
  __half2* ks = (__half2*)smem8;   // 7776 half2 = 31104 bytes
  for (int i = threadIdx.x; i < 7776; i += 256) {
    float2 f = ((const float2*)cb)[i];
    ks[i] = __floats2half2_rn(f.x, f.y);
  }
  __syncthreads();

  const int lane = threadIdx.x & 31;
  const int w    = threadIdx.x >> 5;
  const int n0   = blockIdx.x * 128 + w * 16;

  for (int pi = 0; pi < 16; ++pi) {
    int n = n0 + pi;
    if (n >= NPTS) break;
    float agg[6] = {0.f,0.f,0.f,0.f,0.f,0.f};
    #pragma unroll
    for (int d = 0; d < 3; ++d) {
      const int* nd = neis + d*KTAP*NPTS + n;
      int rr[KTAP];
      #pragma unroll
      for (int k = 0; k < KTAP; ++k) rr[k] = __ldg(&nd[k*NPTS]);
      float pd[6] = {0.f,0.f,0.f,0.f,0.f,0.f};
      #pragma unroll 9
      for (int k = 0; k < KTAP; ++k) {
        int r = rr[k];
        if (r < NPTS) {
          const __half2* vr = (const __half2*)(g_v2h + (size_t)r * DIMC);
          const __half2* kk = ks + (d*KTAP + k)*96;
          #pragma unroll
          for (int i = 0; i < 3; ++i) {
            float2 f = __half22float2(vr[lane + 32*i]);
            float2 kf = __half22float2(kk[lane + 32*i]);
            pd[2*i]   = fmaf(kf.x, f.x, pd[2*i]);
            pd[2*i+1] = fmaf(kf.y, f.y, pd[2*i+1]);
          }
        }
      }
      #pragma unroll
      for (int i = 0; i < 3; ++i) {
        int c = lane*2 + 64*i;
        float ch = g_choice[n*24 + d*8 + (c/24)];
        agg[2*i]   += pd[2*i]   * ch;
        agg[2*i+1] += pd[2*i+1] * ch;
      }
    }
    #pragma unroll
    for (int i = 0; i < 3; ++i) {
      int c = lane*2 + 64*i;
      *(__half2*)&g_aggh[(size_t)n*DIMC + c] =
          __floats2half2_rn(agg[2*i], agg[2*i+1]);
    }
  }
}

// =============================================================================
// K5 (fp16 mma): out = relu(BN( aggh @ out_w )) + x
// =============================================================================
#define K5_APAD 200
#define K5_SMEM ((128 + 96) * K5_APAD * 2)

__global__ __launch_bounds__(256) void k5_mma(
    const float* __restrict__ x, const float* __restrict__ bng,
    const float* __restrict__ bnb, float* __restrict__ out)
{
  extern __shared__ char smem8[];
  __half* As = (__half*)smem8;
  __half* Bs = As + 128 * K5_APAD;
  const int tid  = threadIdx.x;
  const int lane = tid & 31;
  const int wid  = tid >> 5;
  const int wm   = wid & 3;
  const int wn   = wid >> 2;
  const int n0   = blockIdx.x * 128;

  #pragma unroll
  for (int j = 0; j < 12; ++j) {
    int idx = tid + j * 256;
    int row = idx / 24, q = idx % 24;
    int n = n0 + row;
    cpa16z(As + row * K5_APAD + q * 8,
           g_aggh + (size_t)(n < NPTS ? n : 0) * DIMC + q * 8,
           (n < NPTS) ? 16 : 0);
  }
  #pragma unroll
  for (int j = 0; j < 9; ++j) {
    int idx = tid + j * 256;
    int row = idx / 24, q = idx % 24;
    cpa16(Bs + row * K5_APAD + q * 8, g_owh + row * DIMC + q * 8);
  }
  CPA_COMMIT(); CPA_WAIT0();
  __syncthreads();

  float d[2][6][4] = {};
  #pragma unroll
  for (int ks = 0; ks < 12; ++ks) {
    unsigned a[2][4];
    {
      int c0 = ks * 16 + (lane & 3) * 2;
      #pragma unroll
      for (int mi = 0; mi < 2; ++mi) {
        int r = wm * 32 + mi * 16 + (lane >> 2);
        a[mi][0] = *(const unsigned*)&As[r * K5_APAD + c0];
        a[mi][1] = *(const unsigned*)&As[(r + 8) * K5_APAD + c0];
        a[mi][2] = *(const unsigned*)&As[r * K5_APAD + c0 + 8];
        a[mi][3] = *(const unsigned*)&As[(r + 8) * K5_APAD + c0 + 8];
      }
    }
    unsigned bf[6][2];
    {
      int kk = ks * 16 + (lane & 3) * 2;
      #pragma unroll
      for (int ni = 0; ni < 6; ++ni) {
        int n = wn * 48 + ni * 8 + (lane >> 2);
        bf[ni][0] = *(const unsigned*)&Bs[n * K5_APAD + kk];
        bf[ni][1] = *(const unsigned*)&Bs[n * K5_APAD + kk + 8];
      }
    }
    #pragma unroll
    for (int mi = 0; mi < 2; ++mi)
      #pragma unroll
      for (int ni = 0; ni < 6; ++ni)
        mma_f16(d[mi][ni], a[mi], bf[ni]);
  }

  #pragma unroll
  for (int mi = 0; mi < 2; ++mi) {
    int r0 = n0 + wm * 32 + mi * 16 + (lane >> 2);
    #pragma unroll
    for (int ni = 0; ni < 6; ++ni) {
      int c = wn * 48 + ni * 8 + (lane & 3) * 2;
      float g0 = __ldg(&bng[c]),     b0 = __ldg(&bnb[c]);
      float g1 = __ldg(&bng[c + 1]), b1 = __ldg(&bnb[c + 1]);
      if (r0 < NPTS) {
        float2 v;
        v.x = fmaxf(fmaf(d[mi][ni][0], g0, b0), 0.f) + x[(size_t)r0 * PCH + c];
        v.y = fmaxf(fmaf(d[mi][ni][1], g1, b1), 0.f) + x[(size_t)r0 * PCH + c + 1];
        *(float2*)&out[(size_t)r0 * PCH + c] = v;
      }
      if (r0 + 8 < NPTS) {
        float2 v;
        v.x = fmaxf(fmaf(d[mi][ni][2], g0, b0), 0.f) + x[(size_t)(r0+8) * PCH + c];
        v.y = fmaxf(fmaf(d[mi][ni][3], g1, b1), 0.f) + x[(size_t)(r0+8) * PCH + c + 1];
        *(float2*)&out[(size_t)(r0 + 8) * PCH + c] = v;
      }
    }
  }
}

// =============================================================================
extern "C" void kernel_launch(void* const* d_in, const int* in_sizes, int n_in,
                              void* d_out, int out_size)
{
  const float* x    = (const float*)d_in[0];
  const int*   neis = (const int*)  d_in[1];
  const float* w_v1 = (const float*)d_in[2];
  const float* bn1g = (const float*)d_in[3];
  const float* bn1b = (const float*)d_in[4];
  const float* w_v2 = (const float*)d_in[5];
  const float* bn2g = (const float*)d_in[6];
  const float* bn2b = (const float*)d_in[7];
  const float* q_w  = (const float*)d_in[8];
  const float* cbk  = (const float*)d_in[9];
  const float* outw = (const float*)d_in[10];
  const float* obng = (const float*)d_in[11];
  const float* obnb = (const float*)d_in[12];
  float* out = (float*)d_out;

  cudaFuncSetAttribute(k1_mma,   cudaFuncAttributeMaxDynamicSharedMemorySize, K1_SMEM);
  cudaFuncSetAttribute(k2_mma,   cudaFuncAttributeMaxDynamicSharedMemorySize, K2_SMEM);
  cudaFuncSetAttribute(k3_choice,cudaFuncAttributeMaxDynamicSharedMemorySize, K3_SMEM);
  cudaFuncSetAttribute(k4_agg,   cudaFuncAttributeMaxDynamicSharedMemorySize, K4_SMEM);
  cudaFuncSetAttribute(k5_mma,   cudaFuncAttributeMaxDynamicSharedMemorySize, K5_SMEM);

  // order chosen so launch #6 (ncu -s 5 -c 1) is k3_choice
  k0_cvt_x  <<<512, 256>>>(x);
  k0_cvt_w1 <<<KTAP, 256>>>(w_v1);
  k0_cvt_qw <<<3 * KTAP, 256>>>(q_w);
  k0_cvt_w2 <<<(PCH * DIMC + 255) / 256, 256>>>(w_v2);
  k0_cvt_ow <<<(PCH * DIMC + 255) / 256, 256>>>(outw);

  k3_choice <<<(NPTS + 127) / 128, 256, K3_SMEM>>>(neis);
  k1_mma    <<<(NPTS + 127) / 128, 256, K1_SMEM>>>(neis, bn1g, bn1b);
  k2_mma    <<<dim3((NPTS + 127) / 128, 2), 256, K2_SMEM>>>(bn2g, bn2b);
  k4_agg    <<<(NPTS + 127) / 128, 256, K4_SMEM>>>(neis, cbk);
  k5_mma    <<<(NPTS + 127) / 128, 256, K5_SMEM>>>(x, obng, obnb, out);
}